// round 11
// baseline (speedup 1.0000x reference)
#include <cuda_runtime.h>
#include <cuda_fp16.h>
#include <cstdint>
#include <math.h>

#define Bsz 8
#define Lsz 1024
#define Esz 1024
#define Hsz 16
#define DHsz 64
#define FFsz 4096
#define Msz (Bsz*Lsz) /* 8192 */

// ---------------- scratch (device globals; no allocation) ----------------
__device__ __align__(256) float  g_res1[Msz*Esz];
__device__ __align__(256) float  g_ln1[Msz*Esz];
__device__ __align__(256) float  g_res2[Msz*Esz];
__device__ __align__(256) __half g_xh[Msz*Esz];
__device__ __align__(256) __half g_qkvh[(size_t)Msz*3*Esz];
__device__ __align__(256) __half g_atth[Msz*Esz];
__device__ __align__(256) __half g_ln1h[Msz*Esz];
__device__ __align__(256) __half g_hidh[(size_t)Msz*FFsz];
__device__ __align__(256) __half g_wqkvT[(size_t)3*Esz*Esz];
__device__ __align__(256) float  g_bqkv[3*Esz];
__device__ __align__(256) __half g_woT[Esz*Esz];
__device__ __align__(256) __half g_w1T[(size_t)FFsz*Esz];
__device__ __align__(256) __half g_w2T[(size_t)Esz*FFsz];

// ---------------- helpers ----------------
__device__ __forceinline__ uint32_t smem_u32(const void* p) {
    uint32_t a;
    asm("{ .reg .u64 t; cvta.to.shared.u64 t, %1; cvt.u32.u64 %0, t; }" : "=r"(a) : "l"(p));
    return a;
}
#define CP16(dst, src) \
    asm volatile("cp.async.cg.shared.global [%0], [%1], 16;" :: "r"(dst), "l"(src))
#define CP_COMMIT() asm volatile("cp.async.commit_group;" ::: "memory")
#define CP_WAIT2()  asm volatile("cp.async.wait_group 2;"  ::: "memory")
#define CP_WAIT1()  asm volatile("cp.async.wait_group 1;"  ::: "memory")
#define CP_WAIT0()  asm volatile("cp.async.wait_group 0;"  ::: "memory")

__device__ __forceinline__ void ldsm4(uint32_t* r, uint32_t addr) {
    asm volatile("ldmatrix.sync.aligned.m8n8.x4.shared.b16 {%0,%1,%2,%3}, [%4];"
        : "=r"(r[0]), "=r"(r[1]), "=r"(r[2]), "=r"(r[3]) : "r"(addr));
}
__device__ __forceinline__ void ldsm4t(uint32_t* r, uint32_t addr) {
    asm volatile("ldmatrix.sync.aligned.m8n8.x4.trans.shared.b16 {%0,%1,%2,%3}, [%4];"
        : "=r"(r[0]), "=r"(r[1]), "=r"(r[2]), "=r"(r[3]) : "r"(addr));
}
__device__ __forceinline__ void mma16(float* c, const uint32_t* a, const uint32_t* b) {
    asm volatile(
        "mma.sync.aligned.m16n8k16.row.col.f32.f16.f16.f32 "
        "{%0,%1,%2,%3}, {%4,%5,%6,%7}, {%8,%9}, {%0,%1,%2,%3};"
        : "+f"(c[0]), "+f"(c[1]), "+f"(c[2]), "+f"(c[3])
        : "r"(a[0]), "r"(a[1]), "r"(a[2]), "r"(a[3]), "r"(b[0]), "r"(b[1]));
}
__device__ __forceinline__ uint32_t packh2(float a, float b) {
    __half2 h = __floats2half2_rn(a, b);
    return *(uint32_t*)&h;
}

// ================= fp16 GEMM: CTA 128x256, warp 64x64, 4-stage ===========
#define GROW_B 144
#define GA_TILE_B (128 * GROW_B)                 /* 18432 */
#define GB_TILE_B (256 * GROW_B)                 /* 36864 */
#define GSTAGE_B (GA_TILE_B + GB_TILE_B)         /* 55296 */
#define GSMEM_BYTES (4 * GSTAGE_B)               /* 221184 */

template<int EPI, int WF32, int WH>
__global__ __launch_bounds__(256, 1)
void gemm_h(const __half* __restrict__ A, const __half* __restrict__ Bt,
            const float* __restrict__ bias, const float* __restrict__ R,
            float* __restrict__ C, __half* __restrict__ Ch, int M, int N, int K)
{
    extern __shared__ __align__(16) char hs[];
    const uint32_t sbase = smem_u32(hs);

    const int tid  = threadIdx.x;
    const int lane = tid & 31;
    const int wid  = tid >> 5;
    const int g    = lane >> 2;
    const int tig  = lane & 3;
    const int wm   = (wid & 1) * 64;
    const int wn   = (wid >> 1) * 64;
    const int m0   = blockIdx.y * 128;
    const int n0   = blockIdx.x * 256;

    const __half* Ab = A  + (size_t)m0 * K;
    const __half* Bb = Bt + (size_t)n0 * K;

    auto load_stage = [&](int s, int k0) {
        const uint32_t sa = sbase + (uint32_t)s * GSTAGE_B;
        const uint32_t sb = sa + GA_TILE_B;
#pragma unroll
        for (int i = 0; i < 4; i++) {             // A: 128 rows x 8 chunks
            const int id = i * 256 + tid;
            const int row = id >> 3, c = id & 7;
            CP16(sa + (uint32_t)row * GROW_B + (uint32_t)c * 16,
                 Ab + (size_t)row * K + k0 + c * 8);
        }
#pragma unroll
        for (int i = 0; i < 8; i++) {             // B: 256 rows x 8 chunks
            const int id = i * 256 + tid;
            const int row = id >> 3, c = id & 7;
            CP16(sb + (uint32_t)row * GROW_B + (uint32_t)c * 16,
                 Bb + (size_t)row * K + k0 + c * 8);
        }
    };

    const int a_r  = wm + (lane & 15);
    const int a_c  = 8 * (lane >> 4);
    const int b_r  = wn + (lane & 7) + ((lane >> 4) & 1) * 8;   // + p*16
    const int b_c  = 8 * ((lane >> 3) & 1);

    float acc[4][8][4];
#pragma unroll
    for (int i = 0; i < 4; i++)
#pragma unroll
        for (int j = 0; j < 8; j++)
#pragma unroll
            for (int l = 0; l < 4; l++) acc[i][j][l] = 0.f;

    const int nch = K >> 6;
    load_stage(0, 0);   CP_COMMIT();
    load_stage(1, 64);  CP_COMMIT();
    load_stage(2, 128); CP_COMMIT();

    for (int i = 0; i < nch; i++) {
        if (i + 2 < nch)      { CP_WAIT2(); }
        else if (i + 1 < nch) { CP_WAIT1(); }
        else                  { CP_WAIT0(); }
        __syncthreads();

        if (i + 3 < nch) { load_stage((i + 3) & 3, (i + 3) * 64); CP_COMMIT(); }

        const uint32_t sa = sbase + (uint32_t)(i & 3) * GSTAGE_B;
        const uint32_t sb = sa + GA_TILE_B;
#pragma unroll
        for (int kk = 0; kk < 4; kk++) {
            const int kh = kk * 16;
            uint32_t a[4][4];
#pragma unroll
            for (int mt = 0; mt < 4; mt++)
                ldsm4(a[mt], sa + (uint32_t)(a_r + mt * 16) * GROW_B + (uint32_t)(kh + a_c) * 2);
            uint32_t bf[4][4];
#pragma unroll
            for (int p = 0; p < 4; p++)
                ldsm4(bf[p], sb + (uint32_t)(b_r + p * 16) * GROW_B + (uint32_t)(kh + b_c) * 2);
#pragma unroll
            for (int mt = 0; mt < 4; mt++)
#pragma unroll
                for (int p = 0; p < 4; p++) {
                    mma16(acc[mt][2 * p],     a[mt], &bf[p][0]);
                    mma16(acc[mt][2 * p + 1], a[mt], &bf[p][2]);
                }
        }
    }

#pragma unroll
    for (int mt = 0; mt < 4; mt++) {
        const int r0 = m0 + wm + mt * 16 + g;
        const int r1 = r0 + 8;
#pragma unroll
        for (int nt = 0; nt < 8; nt++) {
            const int c0 = n0 + wn + nt * 8 + 2 * tig;
            const float2 bb = *(const float2*)(bias + c0);
            float v00 = acc[mt][nt][0] + bb.x;
            float v01 = acc[mt][nt][1] + bb.y;
            float v10 = acc[mt][nt][2] + bb.x;
            float v11 = acc[mt][nt][3] + bb.y;
            if (EPI == 1) {
                v00 = fmaxf(v00, 0.f); v01 = fmaxf(v01, 0.f);
                v10 = fmaxf(v10, 0.f); v11 = fmaxf(v11, 0.f);
            }
            if (EPI == 2) {
                const float2 q0 = *(const float2*)(R + (size_t)r0 * N + c0);
                const float2 q1 = *(const float2*)(R + (size_t)r1 * N + c0);
                v00 += q0.x; v01 += q0.y; v10 += q1.x; v11 += q1.y;
            }
            if (WF32) {
                *(float2*)(C + (size_t)r0 * N + c0) = make_float2(v00, v01);
                *(float2*)(C + (size_t)r1 * N + c0) = make_float2(v10, v11);
            }
            if (WH) {
                *(__half2*)(Ch + (size_t)r0 * N + c0) = __floats2half2_rn(v00, v01);
                *(__half2*)(Ch + (size_t)r1 * N + c0) = __floats2half2_rn(v10, v11);
            }
        }
    }
}

// ================= tensor-core flash attention (ldq = packed stride) =====
#define AQ_H   (128 * 72)
#define AKV_H  (64 * 72)
#define ATT_SMEM_BYTES ((AQ_H + 4 * AKV_H) * 2)   /* 55296 */

__global__ __launch_bounds__(256)
void attn_mma(const __half* __restrict__ Qh, const __half* __restrict__ Kh,
              const __half* __restrict__ Vh, __half* __restrict__ O, int ldq)
{
    extern __shared__ __align__(16) __half ash[];
    const uint32_t sb = smem_u32(ash);
    const uint32_t sQ = sb;

    const int qt = blockIdx.x, h = blockIdx.y, b = blockIdx.z;
    const int tid  = threadIdx.x;
    const int lane = tid & 31;
    const int wid  = tid >> 5;
    const int g    = lane >> 2;
    const int tig  = lane & 3;
    const int wq   = wid * 16;

    const size_t qgbase = ((size_t)(b * Lsz + qt * 128)) * ldq + h * 64;

    auto sKs = [&](int s) { return sb + (uint32_t)(AQ_H + s * AKV_H) * 2; };
    auto sVs = [&](int s) { return sb + (uint32_t)(AQ_H + 2 * AKV_H + s * AKV_H) * 2; };

    auto loadQ = [&]() {
#pragma unroll
        for (int i = 0; i < 4; i++) {
            const int id = i * 256 + tid;
            const int row = id >> 3, cc = id & 7;
            CP16(sQ + (uint32_t)row * 144 + (uint32_t)cc * 16,
                 Qh + qgbase + (size_t)row * ldq + cc * 8);
        }
    };
    auto loadKV = [&](int s, int t) {
        const size_t kb = ((size_t)(b * Lsz + t * 64)) * ldq + h * 64;
#pragma unroll
        for (int i = 0; i < 2; i++) {
            const int id = i * 256 + tid;
            const int row = id >> 3, cc = id & 7;
            const uint32_t off = (uint32_t)row * 144 + (uint32_t)cc * 16;
            CP16(sKs(s) + off, Kh + kb + (size_t)row * ldq + cc * 8);
            CP16(sVs(s) + off, Vh + kb + (size_t)row * ldq + cc * 8);
        }
    };

    const uint32_t qa_row = (uint32_t)(wq + (lane & 15));
    const uint32_t qa_col = (uint32_t)(8 * (lane >> 4));
    const uint32_t kb_row = (uint32_t)((lane & 7) + ((lane >> 4) & 1) * 8);
    const uint32_t kb_col = (uint32_t)(8 * ((lane >> 3) & 1));
    const uint32_t vt_row = (uint32_t)((lane & 7) + ((lane >> 3) & 1) * 8);
    const uint32_t vt_col = (uint32_t)((lane >> 4) * 8);

    uint32_t qf[4][4];
    float oacc[8][4];
#pragma unroll
    for (int t = 0; t < 8; t++)
#pragma unroll
        for (int i = 0; i < 4; i++) oacc[t][i] = 0.f;
    float m0 = -1e30f, m1 = -1e30f, l0 = 0.f, l1 = 0.f;
    const float scale = 0.125f;

    loadQ(); loadKV(0, 0); CP_COMMIT();
    loadKV(1, 1); CP_COMMIT();

    for (int t = 0; t < Lsz / 64; t++) {
        const int s = t & 1;
        if (t + 1 < Lsz / 64) { CP_WAIT1(); } else { CP_WAIT0(); }
        __syncthreads();

        if (t == 0) {
#pragma unroll
            for (int ks = 0; ks < 4; ks++)
                ldsm4(qf[ks], sQ + qa_row * 144 + (qa_col + 16 * ks) * 2);
        }

        float sacc[8][4];
#pragma unroll
        for (int n = 0; n < 8; n++)
#pragma unroll
            for (int i = 0; i < 4; i++) sacc[n][i] = 0.f;
#pragma unroll
        for (int ks = 0; ks < 4; ks++) {
#pragma unroll
            for (int g16 = 0; g16 < 4; g16++) {
                uint32_t kf[4];
                ldsm4(kf, sKs(s) + (kb_row + g16 * 16) * 144 + (kb_col + 16 * ks) * 2);
                mma16(sacc[2 * g16],     qf[ks], &kf[0]);
                mma16(sacc[2 * g16 + 1], qf[ks], &kf[2]);
            }
        }

        float mx0 = -1e30f, mx1 = -1e30f;
#pragma unroll
        for (int n = 0; n < 8; n++) {
            sacc[n][0] *= scale; sacc[n][1] *= scale;
            sacc[n][2] *= scale; sacc[n][3] *= scale;
            mx0 = fmaxf(mx0, fmaxf(sacc[n][0], sacc[n][1]));
            mx1 = fmaxf(mx1, fmaxf(sacc[n][2], sacc[n][3]));
        }
        mx0 = fmaxf(mx0, __shfl_xor_sync(0xffffffffu, mx0, 1));
        mx0 = fmaxf(mx0, __shfl_xor_sync(0xffffffffu, mx0, 2));
        mx1 = fmaxf(mx1, __shfl_xor_sync(0xffffffffu, mx1, 1));
        mx1 = fmaxf(mx1, __shfl_xor_sync(0xffffffffu, mx1, 2));

        const float mn0 = fmaxf(m0, mx0), mn1 = fmaxf(m1, mx1);
        const float c0 = __expf(m0 - mn0), c1 = __expf(m1 - mn1);
        m0 = mn0; m1 = mn1;

        uint32_t ph[8][2];
        float l0a = 0.f, l1a = 0.f;
#pragma unroll
        for (int n = 0; n < 8; n++) {
            const float p00 = __expf(sacc[n][0] - mn0);
            const float p01 = __expf(sacc[n][1] - mn0);
            const float p10 = __expf(sacc[n][2] - mn1);
            const float p11 = __expf(sacc[n][3] - mn1);
            l0a += p00 + p01; l1a += p10 + p11;
            ph[n][0] = packh2(p00, p01);
            ph[n][1] = packh2(p10, p11);
        }
        l0a += __shfl_xor_sync(0xffffffffu, l0a, 1);
        l0a += __shfl_xor_sync(0xffffffffu, l0a, 2);
        l1a += __shfl_xor_sync(0xffffffffu, l1a, 1);
        l1a += __shfl_xor_sync(0xffffffffu, l1a, 2);
        l0 = l0 * c0 + l0a; l1 = l1 * c1 + l1a;

#pragma unroll
        for (int n = 0; n < 8; n++) {
            oacc[n][0] *= c0; oacc[n][1] *= c0;
            oacc[n][2] *= c1; oacc[n][3] *= c1;
        }

#pragma unroll
        for (int j = 0; j < 4; j++) {
            const uint32_t pa[4] = { ph[2 * j][0], ph[2 * j][1],
                                     ph[2 * j + 1][0], ph[2 * j + 1][1] };
#pragma unroll
            for (int g16 = 0; g16 < 4; g16++) {
                uint32_t vf[4];
                ldsm4t(vf, sVs(s) + (vt_row + j * 16) * 144 + (vt_col + g16 * 16) * 2);
                mma16(oacc[2 * g16],     pa, &vf[0]);
                mma16(oacc[2 * g16 + 1], pa, &vf[2]);
            }
        }

        __syncthreads();
        if (t + 2 < Lsz / 64) { loadKV(s, t + 2); CP_COMMIT(); }
    }

    const float i0 = 1.f / l0, i1 = 1.f / l1;
    const size_t r0 = (size_t)(b * Lsz + qt * 128 + wq + g) * Esz + h * 64;
    const size_t r1 = r0 + (size_t)8 * Esz;
#pragma unroll
    for (int n = 0; n < 8; n++) {
        const int col = 8 * n + 2 * tig;
        *(__half2*)(O + r0 + col) = __floats2half2_rn(oacc[n][0] * i0, oacc[n][1] * i0);
        *(__half2*)(O + r1 + col) = __floats2half2_rn(oacc[n][2] * i1, oacc[n][3] * i1);
    }
}

// ================= fused prep =================
__device__ __forceinline__ void tr_body(const float* in, __half* out, int K, int N,
                                        int k0, int n0, int tx, int ty)
{
    __shared__ float t[32][33];
#pragma unroll
    for (int i = 0; i < 4; i++)
        t[ty + 8 * i][tx] = in[(size_t)(k0 + ty + 8 * i) * N + n0 + tx];
    __syncthreads();
#pragma unroll
    for (int i = 0; i < 4; i++)
        out[(size_t)(n0 + ty + 8 * i) * K + k0 + tx] = __float2half_rn(t[tx][ty + 8 * i]);
}

__global__ void prep_all(const float* __restrict__ x,   __half* __restrict__ xh,
                         const float* __restrict__ Wq,  const float* __restrict__ Wk,
                         const float* __restrict__ Wv,  __half* __restrict__ wqkvT,
                         const float* __restrict__ Wo,  __half* __restrict__ woT,
                         const float* __restrict__ W1,  __half* __restrict__ w1T,
                         const float* __restrict__ W2,  __half* __restrict__ w2T,
                         const float* __restrict__ bq,  const float* __restrict__ bk,
                         const float* __restrict__ bv,  float* __restrict__ bqkv)
{
    const int tx = threadIdx.x, ty = threadIdx.y;
    int bx = blockIdx.x;
    if (bx < 8192) {
        const int i = bx * 256 + ty * 32 + tx;
        const float4 v = ((const float4*)x)[i];
        ((__half2*)xh)[2 * i]     = __floats2half2_rn(v.x, v.y);
        ((__half2*)xh)[2 * i + 1] = __floats2half2_rn(v.z, v.w);
        return;
    }
    bx -= 8192;
    if (bx < 3072) {   // headed QKV transposes -> combined [3072][1024]
        const int which = bx >> 10;
        const int r = bx & 1023;
        const int e0 = (r & 31) * 32, d0 = ((r >> 5) & 1) * 32, h = r >> 6;
        const float* W = (which == 0) ? Wq : (which == 1) ? Wk : Wv;
        __shared__ float t[32][33];
        const float* ih = W + (size_t)h * Esz * 64;
#pragma unroll
        for (int i = 0; i < 4; i++)
            t[ty + 8 * i][tx] = ih[(size_t)(e0 + ty + 8 * i) * 64 + d0 + tx];
        __syncthreads();
#pragma unroll
        for (int i = 0; i < 4; i++)
            wqkvT[(size_t)(which * Esz + h * 64 + d0 + ty + 8 * i) * Esz + e0 + tx] =
                __float2half_rn(t[tx][ty + 8 * i]);
        return;
    }
    bx -= 3072;
    if (bx < 1024) { tr_body(Wo, woT, Esz, Esz, (bx & 31) * 32, (bx >> 5) * 32, tx, ty); return; }
    bx -= 1024;
    if (bx < 4096) { tr_body(W1, w1T, Esz, FFsz, (bx & 31) * 32, (bx >> 5) * 32, tx, ty); return; }
    bx -= 4096;
    if (bx < 4096) { tr_body(W2, w2T, FFsz, Esz, (bx & 127) * 32, (bx >> 7) * 32, tx, ty); return; }
    // bias concat block
    const int id = ty * 32 + tx;
#pragma unroll
    for (int j = 0; j < 12; j++) {
        const int idx = j * 256 + id;
        bqkv[idx] = (idx < 1024) ? bq[idx] : (idx < 2048) ? bk[idx - 1024] : bv[idx - 2048];
    }
}

// ================= layer norm =================
__global__ __launch_bounds__(256)
void ln_kernel(const float* __restrict__ X, const float* __restrict__ gamma,
               const float* __restrict__ beta, float* __restrict__ Y,
               __half* __restrict__ Yh)
{
    const int row = blockIdx.x;
    const int tid = threadIdx.x;
    const float4 v = ((const float4*)(X + (size_t)row * Esz))[tid];
    float s  = v.x + v.y + v.z + v.w;
    float ss = v.x * v.x + v.y * v.y + v.z * v.z + v.w * v.w;
#pragma unroll
    for (int off = 16; off; off >>= 1) {
        s  += __shfl_xor_sync(0xffffffffu, s,  off);
        ss += __shfl_xor_sync(0xffffffffu, ss, off);
    }
    __shared__ float sh[16];
    const int w = tid >> 5, lane = tid & 31;
    if (lane == 0) { sh[w] = s; sh[w + 8] = ss; }
    __syncthreads();
    if (tid == 0) {
        float S = 0.f, SS = 0.f;
#pragma unroll
        for (int i = 0; i < 8; i++) { S += sh[i]; SS += sh[i + 8]; }
        float mean = S * (1.f / Esz);
        float var  = SS * (1.f / Esz) - mean * mean;
        sh[0] = mean;
        sh[1] = rsqrtf(var + 1e-10f);
    }
    __syncthreads();
    const float mean = sh[0], inv = sh[1];
    const float4 gg = ((const float4*)gamma)[tid];
    const float4 be = ((const float4*)beta)[tid];
    float4 y;
    y.x = gg.x * (v.x - mean) * inv + be.x;
    y.y = gg.y * (v.y - mean) * inv + be.y;
    y.z = gg.z * (v.z - mean) * inv + be.z;
    y.w = gg.w * (v.w - mean) * inv + be.w;
    ((float4*)(Y + (size_t)row * Esz))[tid] = y;
    if (Yh) {
        ((__half2*)(Yh + (size_t)row * Esz))[2 * tid]     = __floats2half2_rn(y.x, y.y);
        ((__half2*)(Yh + (size_t)row * Esz))[2 * tid + 1] = __floats2half2_rn(y.z, y.w);
    }
}

// ================= launch =================
extern "C" void kernel_launch(void* const* d_in, const int* in_sizes, int n_in,
                              void* d_out, int out_size)
{
    const float* x   = (const float*)d_in[0];
    const float* Wq  = (const float*)d_in[1];
    const float* bq  = (const float*)d_in[2];
    const float* Wk  = (const float*)d_in[3];
    const float* bk  = (const float*)d_in[4];
    const float* Wv  = (const float*)d_in[5];
    const float* bv  = (const float*)d_in[6];
    const float* Wo  = (const float*)d_in[7];
    const float* bo  = (const float*)d_in[8];
    const float* W1  = (const float*)d_in[9];
    const float* b1  = (const float*)d_in[10];
    const float* W2  = (const float*)d_in[11];
    const float* b2  = (const float*)d_in[12];
    const float* g1  = (const float*)d_in[13];
    const float* be1 = (const float*)d_in[14];
    const float* g2  = (const float*)d_in[15];
    const float* be2 = (const float*)d_in[16];
    float* out = (float*)d_out;

    float *res1, *ln1, *res2, *bqkv;
    __half *xh, *qkvh, *atth, *ln1h, *hidh, *wqkvT, *woT, *w1T, *w2T;
    cudaGetSymbolAddress((void**)&res1,  g_res1);
    cudaGetSymbolAddress((void**)&ln1,   g_ln1);
    cudaGetSymbolAddress((void**)&res2,  g_res2);
    cudaGetSymbolAddress((void**)&bqkv,  g_bqkv);
    cudaGetSymbolAddress((void**)&xh,    g_xh);
    cudaGetSymbolAddress((void**)&qkvh,  g_qkvh);
    cudaGetSymbolAddress((void**)&atth,  g_atth);
    cudaGetSymbolAddress((void**)&ln1h,  g_ln1h);
    cudaGetSymbolAddress((void**)&hidh,  g_hidh);
    cudaGetSymbolAddress((void**)&wqkvT, g_wqkvT);
    cudaGetSymbolAddress((void**)&woT,   g_woT);
    cudaGetSymbolAddress((void**)&w1T,   g_w1T);
    cudaGetSymbolAddress((void**)&w2T,   g_w2T);

    cudaFuncSetAttribute(gemm_h<0,0,1>, cudaFuncAttributeMaxDynamicSharedMemorySize, GSMEM_BYTES);
    cudaFuncSetAttribute(gemm_h<2,1,0>, cudaFuncAttributeMaxDynamicSharedMemorySize, GSMEM_BYTES);
    cudaFuncSetAttribute(gemm_h<1,0,1>, cudaFuncAttributeMaxDynamicSharedMemorySize, GSMEM_BYTES);
    cudaFuncSetAttribute(attn_mma, cudaFuncAttributeMaxDynamicSharedMemorySize, ATT_SMEM_BYTES);

    // launch 0: fused prep (+1 block for bias concat)
    prep_all<<<20481, dim3(32, 8)>>>(x, xh, Wq, Wk, Wv, wqkvT, Wo, woT,
                                     W1, w1T, W2, w2T, bq, bk, bv, bqkv);

    const dim3 blk(256);

    // launch 1: merged QKV  (N = 3072)
    gemm_h<0,0,1><<<dim3(3 * Esz / 256, Msz / 128), blk, GSMEM_BYTES>>>(
        xh, wqkvT, bqkv, nullptr, nullptr, qkvh, Msz, 3 * Esz, Esz);

    // launch 2: attention (packed stride 3072)
    attn_mma<<<dim3(Lsz / 128, Hsz, Bsz), blk, ATT_SMEM_BYTES>>>(
        qkvh, qkvh + Esz, qkvh + 2 * Esz, atth, 3 * Esz);

    // launch 3: O-projection + residual x
    gemm_h<2,1,0><<<dim3(Esz / 256, Msz / 128), blk, GSMEM_BYTES>>>(
        atth, woT, bo, x, res1, nullptr, Msz, Esz, Esz);
    // launch 4: LN1
    ln_kernel<<<Msz, 256>>>(res1, g1, be1, ln1, ln1h);

    // launch 5: FFN1 (relu, half out)  <-- ncu -s 5 captures this
    gemm_h<1,0,1><<<dim3(FFsz / 256, Msz / 128), blk, GSMEM_BYTES>>>(
        ln1h, w1T, b1, nullptr, nullptr, hidh, Msz, FFsz, Esz);
    // launch 6: FFN2 + residual ln1
    gemm_h<2,1,0><<<dim3(Esz / 256, Msz / 128), blk, GSMEM_BYTES>>>(
        hidh, w2T, b2, ln1, res2, nullptr, Msz, Esz, FFsz);
    ln_kernel<<<Msz, 256>>>(res2, g2, be2, out, nullptr);
}

// round 12
// speedup vs baseline: 1.1383x; 1.1383x over previous
#include <cuda_runtime.h>
#include <cuda_fp16.h>
#include <cstdint>
#include <math.h>

#define Bsz 8
#define Lsz 1024
#define Esz 1024
#define Hsz 16
#define DHsz 64
#define FFsz 4096
#define Msz (Bsz*Lsz) /* 8192 */

// ---------------- scratch (device globals; no allocation) ----------------
__device__ __align__(256) float  g_res1[Msz*Esz];
__device__ __align__(256) float  g_ln1[Msz*Esz];
__device__ __align__(256) float  g_res2[Msz*Esz];
__device__ __align__(256) __half g_xh[Msz*Esz];
__device__ __align__(256) __half g_qkvh[(size_t)Msz*3*Esz];
__device__ __align__(256) __half g_atth[Msz*Esz];
__device__ __align__(256) __half g_ln1h[Msz*Esz];
__device__ __align__(256) __half g_hidh[(size_t)Msz*FFsz];
__device__ __align__(256) __half g_wqkvT[(size_t)3*Esz*Esz];
__device__ __align__(256) float  g_bqkv[3*Esz];
__device__ __align__(256) __half g_woT[Esz*Esz];
__device__ __align__(256) __half g_w1T[(size_t)FFsz*Esz];
__device__ __align__(256) __half g_w2T[(size_t)Esz*FFsz];

// ---------------- helpers ----------------
__device__ __forceinline__ uint32_t smem_u32(const void* p) {
    uint32_t a;
    asm("{ .reg .u64 t; cvta.to.shared.u64 t, %1; cvt.u32.u64 %0, t; }" : "=r"(a) : "l"(p));
    return a;
}
#define CP16(dst, src) \
    asm volatile("cp.async.cg.shared.global [%0], [%1], 16;" :: "r"(dst), "l"(src))
#define CP_COMMIT() asm volatile("cp.async.commit_group;" ::: "memory")
#define CP_WAIT1()  asm volatile("cp.async.wait_group 1;"  ::: "memory")
#define CP_WAIT0()  asm volatile("cp.async.wait_group 0;"  ::: "memory")

__device__ __forceinline__ void ldsm4(uint32_t* r, uint32_t addr) {
    asm volatile("ldmatrix.sync.aligned.m8n8.x4.shared.b16 {%0,%1,%2,%3}, [%4];"
        : "=r"(r[0]), "=r"(r[1]), "=r"(r[2]), "=r"(r[3]) : "r"(addr));
}
__device__ __forceinline__ void ldsm4t(uint32_t* r, uint32_t addr) {
    asm volatile("ldmatrix.sync.aligned.m8n8.x4.trans.shared.b16 {%0,%1,%2,%3}, [%4];"
        : "=r"(r[0]), "=r"(r[1]), "=r"(r[2]), "=r"(r[3]) : "r"(addr));
}
__device__ __forceinline__ void mma16(float* c, const uint32_t* a, const uint32_t* b) {
    asm volatile(
        "mma.sync.aligned.m16n8k16.row.col.f32.f16.f16.f32 "
        "{%0,%1,%2,%3}, {%4,%5,%6,%7}, {%8,%9}, {%0,%1,%2,%3};"
        : "+f"(c[0]), "+f"(c[1]), "+f"(c[2]), "+f"(c[3])
        : "r"(a[0]), "r"(a[1]), "r"(a[2]), "r"(a[3]), "r"(b[0]), "r"(b[1]));
}
__device__ __forceinline__ uint32_t packh2(float a, float b) {
    __half2 h = __floats2half2_rn(a, b);
    return *(uint32_t*)&h;
}

// ================= fp16 GEMM: CTA 128x128, 4 warps of 64x64, 3 stages ====
#define GROW_B 144
#define GTILE_B (128 * GROW_B)        /* 18432 */
#define GSTAGE_B (2 * GTILE_B)        /* 36864 */
#define GSMEM_BYTES (3 * GSTAGE_B)    /* 110592 */

template<int EPI, int WF32, int WH>
__global__ __launch_bounds__(128, 2)
void gemm_h(const __half* __restrict__ A, const __half* __restrict__ Bt,
            const float* __restrict__ bias, const float* __restrict__ R,
            float* __restrict__ C, __half* __restrict__ Ch, int M, int N, int K)
{
    extern __shared__ __align__(16) char hs[];
    const uint32_t sbase = smem_u32(hs);

    const int tid  = threadIdx.x;
    const int lane = tid & 31;
    const int wid  = tid >> 5;          // 0..3
    const int g    = lane >> 2;
    const int tig  = lane & 3;
    const int wm   = (wid & 1) * 64;
    const int wn   = (wid >> 1) * 64;
    const int m0   = blockIdx.y * 128;
    const int n0   = blockIdx.x * 128;

    const __half* Ab = A  + (size_t)m0 * K;
    const __half* Bb = Bt + (size_t)n0 * K;

    // per stage: A,B tiles of 128 rows x 8 x 16B chunks; 128 threads -> 8 iters each
    auto load_stage = [&](int s, int k0) {
        const uint32_t sa = sbase + (uint32_t)s * GSTAGE_B;
        const uint32_t sb = sa + GTILE_B;
#pragma unroll
        for (int i = 0; i < 8; i++) {
            const int id = i * 128 + tid;          // 0..1023
            const int row = id >> 3, c = id & 7;
            const uint32_t off = (uint32_t)row * GROW_B + (uint32_t)c * 16;
            CP16(sa + off, Ab + (size_t)row * K + k0 + c * 8);
            CP16(sb + off, Bb + (size_t)row * K + k0 + c * 8);
        }
    };

    const int a_r  = wm + (lane & 15);
    const int a_c  = 8 * (lane >> 4);
    const int b_r  = wn + (lane & 7) + ((lane >> 4) & 1) * 8;   // + p*16
    const int b_c  = 8 * ((lane >> 3) & 1);

    float acc[4][8][4];
#pragma unroll
    for (int i = 0; i < 4; i++)
#pragma unroll
        for (int j = 0; j < 8; j++)
#pragma unroll
            for (int l = 0; l < 4; l++) acc[i][j][l] = 0.f;

    const int nch = K >> 6;   // 64-half chunks
    load_stage(0, 0);  CP_COMMIT();
    load_stage(1, 64); CP_COMMIT();

    for (int i = 0; i < nch; i++) {
        if (i + 1 < nch) { CP_WAIT1(); } else { CP_WAIT0(); }
        __syncthreads();   // single barrier per chunk (proven in R10)

        if (i + 2 < nch) { load_stage((i + 2) % 3, (i + 2) * 64); CP_COMMIT(); }

        const uint32_t sa = sbase + (uint32_t)(i % 3) * GSTAGE_B;
        const uint32_t sb = sa + GTILE_B;
#pragma unroll
        for (int kk = 0; kk < 4; kk++) {
            const int kh = kk * 16;
            uint32_t a[4][4];
#pragma unroll
            for (int mt = 0; mt < 4; mt++)
                ldsm4(a[mt], sa + (uint32_t)(a_r + mt * 16) * GROW_B + (uint32_t)(kh + a_c) * 2);
            uint32_t bf[4][4];
#pragma unroll
            for (int p = 0; p < 4; p++)
                ldsm4(bf[p], sb + (uint32_t)(b_r + p * 16) * GROW_B + (uint32_t)(kh + b_c) * 2);
#pragma unroll
            for (int mt = 0; mt < 4; mt++)
#pragma unroll
                for (int p = 0; p < 4; p++) {
                    mma16(acc[mt][2 * p],     a[mt], &bf[p][0]);
                    mma16(acc[mt][2 * p + 1], a[mt], &bf[p][2]);
                }
        }
    }

#pragma unroll
    for (int mt = 0; mt < 4; mt++) {
        const int r0 = m0 + wm + mt * 16 + g;
        const int r1 = r0 + 8;
#pragma unroll
        for (int nt = 0; nt < 8; nt++) {
            const int c0 = n0 + wn + nt * 8 + 2 * tig;
            const float2 bb = *(const float2*)(bias + c0);
            float v00 = acc[mt][nt][0] + bb.x;
            float v01 = acc[mt][nt][1] + bb.y;
            float v10 = acc[mt][nt][2] + bb.x;
            float v11 = acc[mt][nt][3] + bb.y;
            if (EPI == 1) {
                v00 = fmaxf(v00, 0.f); v01 = fmaxf(v01, 0.f);
                v10 = fmaxf(v10, 0.f); v11 = fmaxf(v11, 0.f);
            }
            if (EPI == 2) {
                const float2 q0 = *(const float2*)(R + (size_t)r0 * N + c0);
                const float2 q1 = *(const float2*)(R + (size_t)r1 * N + c0);
                v00 += q0.x; v01 += q0.y; v10 += q1.x; v11 += q1.y;
            }
            if (WF32) {
                *(float2*)(C + (size_t)r0 * N + c0) = make_float2(v00, v01);
                *(float2*)(C + (size_t)r1 * N + c0) = make_float2(v10, v11);
            }
            if (WH) {
                *(__half2*)(Ch + (size_t)r0 * N + c0) = __floats2half2_rn(v00, v01);
                *(__half2*)(Ch + (size_t)r1 * N + c0) = __floats2half2_rn(v10, v11);
            }
        }
    }
}

// ================= tensor-core flash attention (ldq = packed stride) =====
#define AQ_H   (128 * 72)
#define AKV_H  (64 * 72)
#define ATT_SMEM_BYTES ((AQ_H + 4 * AKV_H) * 2)   /* 55296 */

__global__ __launch_bounds__(256)
void attn_mma(const __half* __restrict__ Qh, const __half* __restrict__ Kh,
              const __half* __restrict__ Vh, __half* __restrict__ O, int ldq)
{
    extern __shared__ __align__(16) __half ash[];
    const uint32_t sb = smem_u32(ash);
    const uint32_t sQ = sb;

    const int qt = blockIdx.x, h = blockIdx.y, b = blockIdx.z;
    const int tid  = threadIdx.x;
    const int lane = tid & 31;
    const int wid  = tid >> 5;
    const int g    = lane >> 2;
    const int tig  = lane & 3;
    const int wq   = wid * 16;

    const size_t qgbase = ((size_t)(b * Lsz + qt * 128)) * ldq + h * 64;

    auto sKs = [&](int s) { return sb + (uint32_t)(AQ_H + s * AKV_H) * 2; };
    auto sVs = [&](int s) { return sb + (uint32_t)(AQ_H + 2 * AKV_H + s * AKV_H) * 2; };

    auto loadQ = [&]() {
#pragma unroll
        for (int i = 0; i < 4; i++) {
            const int id = i * 256 + tid;
            const int row = id >> 3, cc = id & 7;
            CP16(sQ + (uint32_t)row * 144 + (uint32_t)cc * 16,
                 Qh + qgbase + (size_t)row * ldq + cc * 8);
        }
    };
    auto loadKV = [&](int s, int t) {
        const size_t kb = ((size_t)(b * Lsz + t * 64)) * ldq + h * 64;
#pragma unroll
        for (int i = 0; i < 2; i++) {
            const int id = i * 256 + tid;
            const int row = id >> 3, cc = id & 7;
            const uint32_t off = (uint32_t)row * 144 + (uint32_t)cc * 16;
            CP16(sKs(s) + off, Kh + kb + (size_t)row * ldq + cc * 8);
            CP16(sVs(s) + off, Vh + kb + (size_t)row * ldq + cc * 8);
        }
    };

    const uint32_t qa_row = (uint32_t)(wq + (lane & 15));
    const uint32_t qa_col = (uint32_t)(8 * (lane >> 4));
    const uint32_t kb_row = (uint32_t)((lane & 7) + ((lane >> 4) & 1) * 8);
    const uint32_t kb_col = (uint32_t)(8 * ((lane >> 3) & 1));
    const uint32_t vt_row = (uint32_t)((lane & 7) + ((lane >> 3) & 1) * 8);
    const uint32_t vt_col = (uint32_t)((lane >> 4) * 8);

    uint32_t qf[4][4];
    float oacc[8][4];
#pragma unroll
    for (int t = 0; t < 8; t++)
#pragma unroll
        for (int i = 0; i < 4; i++) oacc[t][i] = 0.f;
    float m0 = -1e30f, m1 = -1e30f, l0 = 0.f, l1 = 0.f;
    const float scale = 0.125f;

    loadQ(); loadKV(0, 0); CP_COMMIT();
    loadKV(1, 1); CP_COMMIT();

    for (int t = 0; t < Lsz / 64; t++) {
        const int s = t & 1;
        if (t + 1 < Lsz / 64) { CP_WAIT1(); } else { CP_WAIT0(); }
        __syncthreads();

        if (t == 0) {
#pragma unroll
            for (int ks = 0; ks < 4; ks++)
                ldsm4(qf[ks], sQ + qa_row * 144 + (qa_col + 16 * ks) * 2);
        }

        float sacc[8][4];
#pragma unroll
        for (int n = 0; n < 8; n++)
#pragma unroll
            for (int i = 0; i < 4; i++) sacc[n][i] = 0.f;
#pragma unroll
        for (int ks = 0; ks < 4; ks++) {
#pragma unroll
            for (int g16 = 0; g16 < 4; g16++) {
                uint32_t kf[4];
                ldsm4(kf, sKs(s) + (kb_row + g16 * 16) * 144 + (kb_col + 16 * ks) * 2);
                mma16(sacc[2 * g16],     qf[ks], &kf[0]);
                mma16(sacc[2 * g16 + 1], qf[ks], &kf[2]);
            }
        }

        float mx0 = -1e30f, mx1 = -1e30f;
#pragma unroll
        for (int n = 0; n < 8; n++) {
            sacc[n][0] *= scale; sacc[n][1] *= scale;
            sacc[n][2] *= scale; sacc[n][3] *= scale;
            mx0 = fmaxf(mx0, fmaxf(sacc[n][0], sacc[n][1]));
            mx1 = fmaxf(mx1, fmaxf(sacc[n][2], sacc[n][3]));
        }
        mx0 = fmaxf(mx0, __shfl_xor_sync(0xffffffffu, mx0, 1));
        mx0 = fmaxf(mx0, __shfl_xor_sync(0xffffffffu, mx0, 2));
        mx1 = fmaxf(mx1, __shfl_xor_sync(0xffffffffu, mx1, 1));
        mx1 = fmaxf(mx1, __shfl_xor_sync(0xffffffffu, mx1, 2));

        const float mn0 = fmaxf(m0, mx0), mn1 = fmaxf(m1, mx1);
        const float c0 = __expf(m0 - mn0), c1 = __expf(m1 - mn1);
        m0 = mn0; m1 = mn1;

        uint32_t ph[8][2];
        float l0a = 0.f, l1a = 0.f;
#pragma unroll
        for (int n = 0; n < 8; n++) {
            const float p00 = __expf(sacc[n][0] - mn0);
            const float p01 = __expf(sacc[n][1] - mn0);
            const float p10 = __expf(sacc[n][2] - mn1);
            const float p11 = __expf(sacc[n][3] - mn1);
            l0a += p00 + p01; l1a += p10 + p11;
            ph[n][0] = packh2(p00, p01);
            ph[n][1] = packh2(p10, p11);
        }
        l0a += __shfl_xor_sync(0xffffffffu, l0a, 1);
        l0a += __shfl_xor_sync(0xffffffffu, l0a, 2);
        l1a += __shfl_xor_sync(0xffffffffu, l1a, 1);
        l1a += __shfl_xor_sync(0xffffffffu, l1a, 2);
        l0 = l0 * c0 + l0a; l1 = l1 * c1 + l1a;

#pragma unroll
        for (int n = 0; n < 8; n++) {
            oacc[n][0] *= c0; oacc[n][1] *= c0;
            oacc[n][2] *= c1; oacc[n][3] *= c1;
        }

#pragma unroll
        for (int j = 0; j < 4; j++) {
            const uint32_t pa[4] = { ph[2 * j][0], ph[2 * j][1],
                                     ph[2 * j + 1][0], ph[2 * j + 1][1] };
#pragma unroll
            for (int g16 = 0; g16 < 4; g16++) {
                uint32_t vf[4];
                ldsm4t(vf, sVs(s) + (vt_row + j * 16) * 144 + (vt_col + g16 * 16) * 2);
                mma16(oacc[2 * g16],     pa, &vf[0]);
                mma16(oacc[2 * g16 + 1], pa, &vf[2]);
            }
        }

        __syncthreads();
        if (t + 2 < Lsz / 64) { loadKV(s, t + 2); CP_COMMIT(); }
    }

    const float i0 = 1.f / l0, i1 = 1.f / l1;
    const size_t r0 = (size_t)(b * Lsz + qt * 128 + wq + g) * Esz + h * 64;
    const size_t r1 = r0 + (size_t)8 * Esz;
#pragma unroll
    for (int n = 0; n < 8; n++) {
        const int col = 8 * n + 2 * tig;
        *(__half2*)(O + r0 + col) = __floats2half2_rn(oacc[n][0] * i0, oacc[n][1] * i0);
        *(__half2*)(O + r1 + col) = __floats2half2_rn(oacc[n][2] * i1, oacc[n][3] * i1);
    }
}

// ================= fused prep =================
__device__ __forceinline__ void tr_body(const float* in, __half* out, int K, int N,
                                        int k0, int n0, int tx, int ty)
{
    __shared__ float t[32][33];
#pragma unroll
    for (int i = 0; i < 4; i++)
        t[ty + 8 * i][tx] = in[(size_t)(k0 + ty + 8 * i) * N + n0 + tx];
    __syncthreads();
#pragma unroll
    for (int i = 0; i < 4; i++)
        out[(size_t)(n0 + ty + 8 * i) * K + k0 + tx] = __float2half_rn(t[tx][ty + 8 * i]);
}

__global__ void prep_all(const float* __restrict__ x,   __half* __restrict__ xh,
                         const float* __restrict__ Wq,  const float* __restrict__ Wk,
                         const float* __restrict__ Wv,  __half* __restrict__ wqkvT,
                         const float* __restrict__ Wo,  __half* __restrict__ woT,
                         const float* __restrict__ W1,  __half* __restrict__ w1T,
                         const float* __restrict__ W2,  __half* __restrict__ w2T,
                         const float* __restrict__ bq,  const float* __restrict__ bk,
                         const float* __restrict__ bv,  float* __restrict__ bqkv)
{
    const int tx = threadIdx.x, ty = threadIdx.y;
    int bx = blockIdx.x;
    if (bx < 8192) {
        const int i = bx * 256 + ty * 32 + tx;
        const float4 v = ((const float4*)x)[i];
        ((__half2*)xh)[2 * i]     = __floats2half2_rn(v.x, v.y);
        ((__half2*)xh)[2 * i + 1] = __floats2half2_rn(v.z, v.w);
        return;
    }
    bx -= 8192;
    if (bx < 3072) {   // headed QKV transposes -> combined [3072][1024]
        const int which = bx >> 10;
        const int r = bx & 1023;
        const int e0 = (r & 31) * 32, d0 = ((r >> 5) & 1) * 32, h = r >> 6;
        const float* W = (which == 0) ? Wq : (which == 1) ? Wk : Wv;
        __shared__ float t[32][33];
        const float* ih = W + (size_t)h * Esz * 64;
#pragma unroll
        for (int i = 0; i < 4; i++)
            t[ty + 8 * i][tx] = ih[(size_t)(e0 + ty + 8 * i) * 64 + d0 + tx];
        __syncthreads();
#pragma unroll
        for (int i = 0; i < 4; i++)
            wqkvT[(size_t)(which * Esz + h * 64 + d0 + ty + 8 * i) * Esz + e0 + tx] =
                __float2half_rn(t[tx][ty + 8 * i]);
        return;
    }
    bx -= 3072;
    if (bx < 1024) { tr_body(Wo, woT, Esz, Esz, (bx & 31) * 32, (bx >> 5) * 32, tx, ty); return; }
    bx -= 1024;
    if (bx < 4096) { tr_body(W1, w1T, Esz, FFsz, (bx & 31) * 32, (bx >> 5) * 32, tx, ty); return; }
    bx -= 4096;
    if (bx < 4096) { tr_body(W2, w2T, FFsz, Esz, (bx & 127) * 32, (bx >> 7) * 32, tx, ty); return; }
    const int id = ty * 32 + tx;
#pragma unroll
    for (int j = 0; j < 12; j++) {
        const int idx = j * 256 + id;
        bqkv[idx] = (idx < 1024) ? bq[idx] : (idx < 2048) ? bk[idx - 1024] : bv[idx - 2048];
    }
}

// ================= layer norm =================
__global__ __launch_bounds__(256)
void ln_kernel(const float* __restrict__ X, const float* __restrict__ gamma,
               const float* __restrict__ beta, float* __restrict__ Y,
               __half* __restrict__ Yh)
{
    const int row = blockIdx.x;
    const int tid = threadIdx.x;
    const float4 v = ((const float4*)(X + (size_t)row * Esz))[tid];
    float s  = v.x + v.y + v.z + v.w;
    float ss = v.x * v.x + v.y * v.y + v.z * v.z + v.w * v.w;
#pragma unroll
    for (int off = 16; off; off >>= 1) {
        s  += __shfl_xor_sync(0xffffffffu, s,  off);
        ss += __shfl_xor_sync(0xffffffffu, ss, off);
    }
    __shared__ float sh[16];
    const int w = tid >> 5, lane = tid & 31;
    if (lane == 0) { sh[w] = s; sh[w + 8] = ss; }
    __syncthreads();
    if (tid == 0) {
        float S = 0.f, SS = 0.f;
#pragma unroll
        for (int i = 0; i < 8; i++) { S += sh[i]; SS += sh[i + 8]; }
        float mean = S * (1.f / Esz);
        float var  = SS * (1.f / Esz) - mean * mean;
        sh[0] = mean;
        sh[1] = rsqrtf(var + 1e-10f);
    }
    __syncthreads();
    const float mean = sh[0], inv = sh[1];
    const float4 gg = ((const float4*)gamma)[tid];
    const float4 be = ((const float4*)beta)[tid];
    float4 y;
    y.x = gg.x * (v.x - mean) * inv + be.x;
    y.y = gg.y * (v.y - mean) * inv + be.y;
    y.z = gg.z * (v.z - mean) * inv + be.z;
    y.w = gg.w * (v.w - mean) * inv + be.w;
    ((float4*)(Y + (size_t)row * Esz))[tid] = y;
    if (Yh) {
        ((__half2*)(Yh + (size_t)row * Esz))[2 * tid]     = __floats2half2_rn(y.x, y.y);
        ((__half2*)(Yh + (size_t)row * Esz))[2 * tid + 1] = __floats2half2_rn(y.z, y.w);
    }
}

// ================= launch =================
extern "C" void kernel_launch(void* const* d_in, const int* in_sizes, int n_in,
                              void* d_out, int out_size)
{
    const float* x   = (const float*)d_in[0];
    const float* Wq  = (const float*)d_in[1];
    const float* bq  = (const float*)d_in[2];
    const float* Wk  = (const float*)d_in[3];
    const float* bk  = (const float*)d_in[4];
    const float* Wv  = (const float*)d_in[5];
    const float* bv  = (const float*)d_in[6];
    const float* Wo  = (const float*)d_in[7];
    const float* bo  = (const float*)d_in[8];
    const float* W1  = (const float*)d_in[9];
    const float* b1  = (const float*)d_in[10];
    const float* W2  = (const float*)d_in[11];
    const float* b2  = (const float*)d_in[12];
    const float* g1  = (const float*)d_in[13];
    const float* be1 = (const float*)d_in[14];
    const float* g2  = (const float*)d_in[15];
    const float* be2 = (const float*)d_in[16];
    float* out = (float*)d_out;

    float *res1, *ln1, *res2, *bqkv;
    __half *xh, *qkvh, *atth, *ln1h, *hidh, *wqkvT, *woT, *w1T, *w2T;
    cudaGetSymbolAddress((void**)&res1,  g_res1);
    cudaGetSymbolAddress((void**)&ln1,   g_ln1);
    cudaGetSymbolAddress((void**)&res2,  g_res2);
    cudaGetSymbolAddress((void**)&bqkv,  g_bqkv);
    cudaGetSymbolAddress((void**)&xh,    g_xh);
    cudaGetSymbolAddress((void**)&qkvh,  g_qkvh);
    cudaGetSymbolAddress((void**)&atth,  g_atth);
    cudaGetSymbolAddress((void**)&ln1h,  g_ln1h);
    cudaGetSymbolAddress((void**)&hidh,  g_hidh);
    cudaGetSymbolAddress((void**)&wqkvT, g_wqkvT);
    cudaGetSymbolAddress((void**)&woT,   g_woT);
    cudaGetSymbolAddress((void**)&w1T,   g_w1T);
    cudaGetSymbolAddress((void**)&w2T,   g_w2T);

    cudaFuncSetAttribute(gemm_h<0,0,1>, cudaFuncAttributeMaxDynamicSharedMemorySize, GSMEM_BYTES);
    cudaFuncSetAttribute(gemm_h<2,1,0>, cudaFuncAttributeMaxDynamicSharedMemorySize, GSMEM_BYTES);
    cudaFuncSetAttribute(gemm_h<1,0,1>, cudaFuncAttributeMaxDynamicSharedMemorySize, GSMEM_BYTES);
    cudaFuncSetAttribute(attn_mma, cudaFuncAttributeMaxDynamicSharedMemorySize, ATT_SMEM_BYTES);

    // launch 0: fused prep (+1 block for bias concat)
    prep_all<<<20481, dim3(32, 8)>>>(x, xh, Wq, Wk, Wv, wqkvT, Wo, woT,
                                     W1, w1T, W2, w2T, bq, bk, bv, bqkv);

    const dim3 blk(128);

    // launch 1: merged QKV  (N = 3072)
    gemm_h<0,0,1><<<dim3(3 * Esz / 128, Msz / 128), blk, GSMEM_BYTES>>>(
        xh, wqkvT, bqkv, nullptr, nullptr, qkvh, Msz, 3 * Esz, Esz);

    // launch 2: attention (packed stride 3072)
    attn_mma<<<dim3(Lsz / 128, Hsz, Bsz), 256, ATT_SMEM_BYTES>>>(
        qkvh, qkvh + Esz, qkvh + 2 * Esz, atth, 3 * Esz);

    // launch 3: O-projection + residual x
    gemm_h<2,1,0><<<dim3(Esz / 128, Msz / 128), blk, GSMEM_BYTES>>>(
        atth, woT, bo, x, res1, nullptr, Msz, Esz, Esz);
    // launch 4: LN1
    ln_kernel<<<Msz, 256>>>(res1, g1, be1, ln1, ln1h);

    // launch 5: FFN1 (relu, half out)  <-- ncu -s 5 captures this
    gemm_h<1,0,1><<<dim3(FFsz / 128, Msz / 128), blk, GSMEM_BYTES>>>(
        ln1h, w1T, b1, nullptr, nullptr, hidh, Msz, FFsz, Esz);
    // launch 6: FFN2 + residual ln1
    gemm_h<2,1,0><<<dim3(Esz / 128, Msz / 128), blk, GSMEM_BYTES>>>(
        hidh, w2T, b2, ln1, res2, nullptr, Msz, Esz, FFsz);
    ln_kernel<<<Msz, 256>>>(res2, g2, be2, out, nullptr);
}

// round 15
// speedup vs baseline: 1.2193x; 1.0712x over previous
#include <cuda_runtime.h>
#include <cuda_fp16.h>
#include <cstdint>
#include <math.h>

#define Bsz 8
#define Lsz 1024
#define Esz 1024
#define Hsz 16
#define DHsz 64
#define FFsz 4096
#define Msz (Bsz*Lsz) /* 8192 */

// ---------------- scratch (device globals; no allocation) ----------------
__device__ __align__(256) float  g_res1[Msz*Esz];
__device__ __align__(256) float  g_ln1[Msz*Esz];
__device__ __align__(256) float  g_res2[Msz*Esz];
__device__ __align__(256) __half g_xh[Msz*Esz];
__device__ __align__(256) __half g_qkvh[(size_t)Msz*3*Esz];
__device__ __align__(256) __half g_atth[Msz*Esz];
__device__ __align__(256) __half g_ln1h[Msz*Esz];
__device__ __align__(256) __half g_hidh[(size_t)Msz*FFsz];
__device__ __align__(256) __half g_wqkvT[(size_t)3*Esz*Esz];
__device__ __align__(256) float  g_bqkv[3*Esz];
__device__ __align__(256) __half g_woT[Esz*Esz];
__device__ __align__(256) __half g_w1T[(size_t)FFsz*Esz];
__device__ __align__(256) __half g_w2T[(size_t)Esz*FFsz];

// ---------------- helpers ----------------
__device__ __forceinline__ uint32_t smem_u32(const void* p) {
    uint32_t a;
    asm("{ .reg .u64 t; cvta.to.shared.u64 t, %1; cvt.u32.u64 %0, t; }" : "=r"(a) : "l"(p));
    return a;
}
#define CP16(dst, src) \
    asm volatile("cp.async.cg.shared.global [%0], [%1], 16;" :: "r"(dst), "l"(src))
#define CP_COMMIT() asm volatile("cp.async.commit_group;" ::: "memory")
#define CP_WAIT1()  asm volatile("cp.async.wait_group 1;"  ::: "memory")
#define CP_WAIT0()  asm volatile("cp.async.wait_group 0;"  ::: "memory")

__device__ __forceinline__ void ldsm4(uint32_t* r, uint32_t addr) {
    asm volatile("ldmatrix.sync.aligned.m8n8.x4.shared.b16 {%0,%1,%2,%3}, [%4];"
        : "=r"(r[0]), "=r"(r[1]), "=r"(r[2]), "=r"(r[3]) : "r"(addr));
}
__device__ __forceinline__ void ldsm4t(uint32_t* r, uint32_t addr) {
    asm volatile("ldmatrix.sync.aligned.m8n8.x4.trans.shared.b16 {%0,%1,%2,%3}, [%4];"
        : "=r"(r[0]), "=r"(r[1]), "=r"(r[2]), "=r"(r[3]) : "r"(addr));
}
__device__ __forceinline__ void mma16(float* c, const uint32_t* a, const uint32_t* b) {
    asm volatile(
        "mma.sync.aligned.m16n8k16.row.col.f32.f16.f16.f32 "
        "{%0,%1,%2,%3}, {%4,%5,%6,%7}, {%8,%9}, {%0,%1,%2,%3};"
        : "+f"(c[0]), "+f"(c[1]), "+f"(c[2]), "+f"(c[3])
        : "r"(a[0]), "r"(a[1]), "r"(a[2]), "r"(a[3]), "r"(b[0]), "r"(b[1]));
}
__device__ __forceinline__ uint32_t packh2(float a, float b) {
    __half2 h = __floats2half2_rn(a, b);
    return *(uint32_t*)&h;
}

// ================= fp16 GEMM: CTA 128x128, 4 warps of 64x64, 3 stages ====
#define GROW_B 144
#define GTILE_B (128 * GROW_B)        /* 18432 */
#define GSTAGE_B (2 * GTILE_B)        /* 36864 */
#define GSMEM_BYTES (3 * GSTAGE_B)    /* 110592 */

template<int EPI, int WF32, int WH>
__global__ __launch_bounds__(128, 2)
void gemm_h(const __half* __restrict__ A, const __half* __restrict__ Bt,
            const float* __restrict__ bias, const float* __restrict__ R,
            float* __restrict__ C, __half* __restrict__ Ch, int M, int N, int K)
{
    extern __shared__ __align__(16) char hs[];
    const uint32_t sbase = smem_u32(hs);

    const int tid  = threadIdx.x;
    const int lane = tid & 31;
    const int wid  = tid >> 5;          // 0..3
    const int g    = lane >> 2;
    const int tig  = lane & 3;
    const int wm   = (wid & 1) * 64;
    const int wn   = (wid >> 1) * 64;
    const int m0   = blockIdx.y * 128;
    const int n0   = blockIdx.x * 128;

    const __half* Ab = A  + (size_t)m0 * K;
    const __half* Bb = Bt + (size_t)n0 * K;

    // load 2 of the 8 per-thread chunk-pairs of a stage (piece = 0..3)
    auto load_piece = [&](int s, int k0, int piece) {
        const uint32_t sa = sbase + (uint32_t)s * GSTAGE_B;
        const uint32_t sb = sa + GTILE_B;
#pragma unroll
        for (int i = piece * 2; i < piece * 2 + 2; i++) {
            const int id = i * 128 + tid;          // 0..1023
            const int row = id >> 3, c = id & 7;
            const uint32_t off = (uint32_t)row * GROW_B + (uint32_t)c * 16;
            CP16(sa + off, Ab + (size_t)row * K + k0 + c * 8);
            CP16(sb + off, Bb + (size_t)row * K + k0 + c * 8);
        }
    };

    const int a_r  = wm + (lane & 15);
    const int a_c  = 8 * (lane >> 4);
    const int b_r  = wn + (lane & 7) + ((lane >> 4) & 1) * 8;   // + p*16
    const int b_c  = 8 * ((lane >> 3) & 1);

    float acc[4][8][4];
#pragma unroll
    for (int i = 0; i < 4; i++)
#pragma unroll
        for (int j = 0; j < 8; j++)
#pragma unroll
            for (int l = 0; l < 4; l++) acc[i][j][l] = 0.f;

    const int nch = K >> 6;   // 64-half chunks
#pragma unroll
    for (int p = 0; p < 4; p++) load_piece(0, 0, p);
    CP_COMMIT();
#pragma unroll
    for (int p = 0; p < 4; p++) load_piece(1, 64, p);
    CP_COMMIT();

    for (int i = 0; i < nch; i++) {
        if (i + 1 < nch) { CP_WAIT1(); } else { CP_WAIT0(); }
        __syncthreads();   // single barrier per chunk

        const bool pf = (i + 2 < nch);
        const int  ps = (i + 2) % 3;
        const int  pk = (i + 2) * 64;

        const uint32_t sa = sbase + (uint32_t)(i % 3) * GSTAGE_B;
        const uint32_t sb = sa + GTILE_B;
#pragma unroll
        for (int kk = 0; kk < 4; kk++) {
            if (pf) load_piece(ps, pk, kk);   // spread cp.async across kk groups
            const int kh = kk * 16;
            uint32_t a[4][4];
#pragma unroll
            for (int mt = 0; mt < 4; mt++)
                ldsm4(a[mt], sa + (uint32_t)(a_r + mt * 16) * GROW_B + (uint32_t)(kh + a_c) * 2);
            uint32_t bf[4][4];
#pragma unroll
            for (int p = 0; p < 4; p++)
                ldsm4(bf[p], sb + (uint32_t)(b_r + p * 16) * GROW_B + (uint32_t)(kh + b_c) * 2);
#pragma unroll
            for (int mt = 0; mt < 4; mt++)
#pragma unroll
                for (int p = 0; p < 4; p++) {
                    mma16(acc[mt][2 * p],     a[mt], &bf[p][0]);
                    mma16(acc[mt][2 * p + 1], a[mt], &bf[p][2]);
                }
        }
        CP_COMMIT();   // one group per iteration (empty near tail is fine)
    }

#pragma unroll
    for (int mt = 0; mt < 4; mt++) {
        const int r0 = m0 + wm + mt * 16 + g;
        const int r1 = r0 + 8;
#pragma unroll
        for (int nt = 0; nt < 8; nt++) {
            const int c0 = n0 + wn + nt * 8 + 2 * tig;
            const float2 bb = *(const float2*)(bias + c0);
            float v00 = acc[mt][nt][0] + bb.x;
            float v01 = acc[mt][nt][1] + bb.y;
            float v10 = acc[mt][nt][2] + bb.x;
            float v11 = acc[mt][nt][3] + bb.y;
            if (EPI == 1) {
                v00 = fmaxf(v00, 0.f); v01 = fmaxf(v01, 0.f);
                v10 = fmaxf(v10, 0.f); v11 = fmaxf(v11, 0.f);
            }
            if (EPI == 2) {
                const float2 q0 = *(const float2*)(R + (size_t)r0 * N + c0);
                const float2 q1 = *(const float2*)(R + (size_t)r1 * N + c0);
                v00 += q0.x; v01 += q0.y; v10 += q1.x; v11 += q1.y;
            }
            if (WF32) {
                *(float2*)(C + (size_t)r0 * N + c0) = make_float2(v00, v01);
                *(float2*)(C + (size_t)r1 * N + c0) = make_float2(v10, v11);
            }
            if (WH) {
                *(__half2*)(Ch + (size_t)r0 * N + c0) = __floats2half2_rn(v00, v01);
                *(__half2*)(Ch + (size_t)r1 * N + c0) = __floats2half2_rn(v10, v11);
            }
        }
    }
}

// ================= tensor-core flash attention (ldq = packed stride) =====
#define AQ_H   (128 * 72)
#define AKV_H  (64 * 72)
#define ATT_SMEM_BYTES ((AQ_H + 4 * AKV_H) * 2)   /* 55296 */

__global__ __launch_bounds__(256)
void attn_mma(const __half* __restrict__ Qh, const __half* __restrict__ Kh,
              const __half* __restrict__ Vh, __half* __restrict__ O, int ldq)
{
    extern __shared__ __align__(16) __half ash[];
    const uint32_t sb = smem_u32(ash);
    const uint32_t sQ = sb;

    const int qt = blockIdx.x, h = blockIdx.y, b = blockIdx.z;
    const int tid  = threadIdx.x;
    const int lane = tid & 31;
    const int wid  = tid >> 5;
    const int g    = lane >> 2;
    const int tig  = lane & 3;
    const int wq   = wid * 16;

    const size_t qgbase = ((size_t)(b * Lsz + qt * 128)) * ldq + h * 64;

    auto sKs = [&](int s) { return sb + (uint32_t)(AQ_H + s * AKV_H) * 2; };
    auto sVs = [&](int s) { return sb + (uint32_t)(AQ_H + 2 * AKV_H + s * AKV_H) * 2; };

    auto loadQ = [&]() {
#pragma unroll
        for (int i = 0; i < 4; i++) {
            const int id = i * 256 + tid;
            const int row = id >> 3, cc = id & 7;
            CP16(sQ + (uint32_t)row * 144 + (uint32_t)cc * 16,
                 Qh + qgbase + (size_t)row * ldq + cc * 8);
        }
    };
    auto loadKV = [&](int s, int t) {
        const size_t kb = ((size_t)(b * Lsz + t * 64)) * ldq + h * 64;
#pragma unroll
        for (int i = 0; i < 2; i++) {
            const int id = i * 256 + tid;
            const int row = id >> 3, cc = id & 7;
            const uint32_t off = (uint32_t)row * 144 + (uint32_t)cc * 16;
            CP16(sKs(s) + off, Kh + kb + (size_t)row * ldq + cc * 8);
            CP16(sVs(s) + off, Vh + kb + (size_t)row * ldq + cc * 8);
        }
    };

    const uint32_t qa_row = (uint32_t)(wq + (lane & 15));
    const uint32_t qa_col = (uint32_t)(8 * (lane >> 4));
    const uint32_t kb_row = (uint32_t)((lane & 7) + ((lane >> 4) & 1) * 8);
    const uint32_t kb_col = (uint32_t)(8 * ((lane >> 3) & 1));
    const uint32_t vt_row = (uint32_t)((lane & 7) + ((lane >> 3) & 1) * 8);
    const uint32_t vt_col = (uint32_t)((lane >> 4) * 8);

    uint32_t qf[4][4];
    float oacc[8][4];
#pragma unroll
    for (int t = 0; t < 8; t++)
#pragma unroll
        for (int i = 0; i < 4; i++) oacc[t][i] = 0.f;
    float m0 = -1e30f, m1 = -1e30f, l0 = 0.f, l1 = 0.f;
    const float scale = 0.125f;

    loadQ(); loadKV(0, 0); CP_COMMIT();
    loadKV(1, 1); CP_COMMIT();

    for (int t = 0; t < Lsz / 64; t++) {
        const int s = t & 1;
        if (t + 1 < Lsz / 64) { CP_WAIT1(); } else { CP_WAIT0(); }
        __syncthreads();

        if (t == 0) {
#pragma unroll
            for (int ks = 0; ks < 4; ks++)
                ldsm4(qf[ks], sQ + qa_row * 144 + (qa_col + 16 * ks) * 2);
        }

        float sacc[8][4];
#pragma unroll
        for (int n = 0; n < 8; n++)
#pragma unroll
            for (int i = 0; i < 4; i++) sacc[n][i] = 0.f;
#pragma unroll
        for (int ks = 0; ks < 4; ks++) {
#pragma unroll
            for (int g16 = 0; g16 < 4; g16++) {
                uint32_t kf[4];
                ldsm4(kf, sKs(s) + (kb_row + g16 * 16) * 144 + (kb_col + 16 * ks) * 2);
                mma16(sacc[2 * g16],     qf[ks], &kf[0]);
                mma16(sacc[2 * g16 + 1], qf[ks], &kf[2]);
            }
        }

        float mx0 = -1e30f, mx1 = -1e30f;
#pragma unroll
        for (int n = 0; n < 8; n++) {
            sacc[n][0] *= scale; sacc[n][1] *= scale;
            sacc[n][2] *= scale; sacc[n][3] *= scale;
            mx0 = fmaxf(mx0, fmaxf(sacc[n][0], sacc[n][1]));
            mx1 = fmaxf(mx1, fmaxf(sacc[n][2], sacc[n][3]));
        }
        mx0 = fmaxf(mx0, __shfl_xor_sync(0xffffffffu, mx0, 1));
        mx0 = fmaxf(mx0, __shfl_xor_sync(0xffffffffu, mx0, 2));
        mx1 = fmaxf(mx1, __shfl_xor_sync(0xffffffffu, mx1, 1));
        mx1 = fmaxf(mx1, __shfl_xor_sync(0xffffffffu, mx1, 2));

        const float mn0 = fmaxf(m0, mx0), mn1 = fmaxf(m1, mx1);
        const float c0 = __expf(m0 - mn0), c1 = __expf(m1 - mn1);
        m0 = mn0; m1 = mn1;

        uint32_t ph[8][2];
        float l0a = 0.f, l1a = 0.f;
#pragma unroll
        for (int n = 0; n < 8; n++) {
            const float p00 = __expf(sacc[n][0] - mn0);
            const float p01 = __expf(sacc[n][1] - mn0);
            const float p10 = __expf(sacc[n][2] - mn1);
            const float p11 = __expf(sacc[n][3] - mn1);
            l0a += p00 + p01; l1a += p10 + p11;
            ph[n][0] = packh2(p00, p01);
            ph[n][1] = packh2(p10, p11);
        }
        l0a += __shfl_xor_sync(0xffffffffu, l0a, 1);
        l0a += __shfl_xor_sync(0xffffffffu, l0a, 2);
        l1a += __shfl_xor_sync(0xffffffffu, l1a, 1);
        l1a += __shfl_xor_sync(0xffffffffu, l1a, 2);
        l0 = l0 * c0 + l0a; l1 = l1 * c1 + l1a;

#pragma unroll
        for (int n = 0; n < 8; n++) {
            oacc[n][0] *= c0; oacc[n][1] *= c0;
            oacc[n][2] *= c1; oacc[n][3] *= c1;
        }

#pragma unroll
        for (int j = 0; j < 4; j++) {
            const uint32_t pa[4] = { ph[2 * j][0], ph[2 * j][1],
                                     ph[2 * j + 1][0], ph[2 * j + 1][1] };
#pragma unroll
            for (int g16 = 0; g16 < 4; g16++) {
                uint32_t vf[4];
                ldsm4t(vf, sVs(s) + (vt_row + j * 16) * 144 + (vt_col + g16 * 16) * 2);
                mma16(oacc[2 * g16],     pa, &vf[0]);
                mma16(oacc[2 * g16 + 1], pa, &vf[2]);
            }
        }

        __syncthreads();
        if (t + 2 < Lsz / 64) { loadKV(s, t + 2); CP_COMMIT(); }
    }

    const float i0 = 1.f / l0, i1 = 1.f / l1;
    const size_t r0 = (size_t)(b * Lsz + qt * 128 + wq + g) * Esz + h * 64;
    const size_t r1 = r0 + (size_t)8 * Esz;
#pragma unroll
    for (int n = 0; n < 8; n++) {
        const int col = 8 * n + 2 * tig;
        *(__half2*)(O + r0 + col) = __floats2half2_rn(oacc[n][0] * i0, oacc[n][1] * i0);
        *(__half2*)(O + r1 + col) = __floats2half2_rn(oacc[n][2] * i1, oacc[n][3] * i1);
    }
}

// ================= prep, split in two =================
__global__ void prep_x(const float* __restrict__ x, __half* __restrict__ xh)
{
    const int i = blockIdx.x * 256 + threadIdx.y * 32 + threadIdx.x;
    const float4 v = ((const float4*)x)[i];
    ((__half2*)xh)[2 * i]     = __floats2half2_rn(v.x, v.y);
    ((__half2*)xh)[2 * i + 1] = __floats2half2_rn(v.z, v.w);
}

__device__ __forceinline__ void tr_body(const float* in, __half* out, int K, int N,
                                        int k0, int n0, int tx, int ty)
{
    __shared__ float t[32][33];
#pragma unroll
    for (int i = 0; i < 4; i++)
        t[ty + 8 * i][tx] = in[(size_t)(k0 + ty + 8 * i) * N + n0 + tx];
    __syncthreads();
#pragma unroll
    for (int i = 0; i < 4; i++)
        out[(size_t)(n0 + ty + 8 * i) * K + k0 + tx] = __float2half_rn(t[tx][ty + 8 * i]);
}

__global__ void prep_w(const float* __restrict__ Wq,  const float* __restrict__ Wk,
                       const float* __restrict__ Wv,  __half* __restrict__ wqkvT,
                       const float* __restrict__ Wo,  __half* __restrict__ woT,
                       const float* __restrict__ W1,  __half* __restrict__ w1T,
                       const float* __restrict__ W2,  __half* __restrict__ w2T,
                       const float* __restrict__ bq,  const float* __restrict__ bk,
                       const float* __restrict__ bv,  float* __restrict__ bqkv)
{
    const int tx = threadIdx.x, ty = threadIdx.y;
    int bx = blockIdx.x;
    if (bx < 3072) {   // headed QKV transposes -> combined [3072][1024]
        const int which = bx >> 10;
        const int r = bx & 1023;
        const int e0 = (r & 31) * 32, d0 = ((r >> 5) & 1) * 32, h = r >> 6;
        const float* W = (which == 0) ? Wq : (which == 1) ? Wk : Wv;
        __shared__ float t[32][33];
        const float* ih = W + (size_t)h * Esz * 64;
#pragma unroll
        for (int i = 0; i < 4; i++)
            t[ty + 8 * i][tx] = ih[(size_t)(e0 + ty + 8 * i) * 64 + d0 + tx];
        __syncthreads();
#pragma unroll
        for (int i = 0; i < 4; i++)
            wqkvT[(size_t)(which * Esz + h * 64 + d0 + ty + 8 * i) * Esz + e0 + tx] =
                __float2half_rn(t[tx][ty + 8 * i]);
        return;
    }
    bx -= 3072;
    if (bx < 1024) { tr_body(Wo, woT, Esz, Esz, (bx & 31) * 32, (bx >> 5) * 32, tx, ty); return; }
    bx -= 1024;
    if (bx < 4096) { tr_body(W1, w1T, Esz, FFsz, (bx & 31) * 32, (bx >> 5) * 32, tx, ty); return; }
    bx -= 4096;
    if (bx < 4096) { tr_body(W2, w2T, FFsz, Esz, (bx & 127) * 32, (bx >> 7) * 32, tx, ty); return; }
    const int id = ty * 32 + tx;
#pragma unroll
    for (int j = 0; j < 12; j++) {
        const int idx = j * 256 + id;
        bqkv[idx] = (idx < 1024) ? bq[idx] : (idx < 2048) ? bk[idx - 1024] : bv[idx - 2048];
    }
}

// ================= layer norm =================
__global__ __launch_bounds__(256)
void ln_kernel(const float* __restrict__ X, const float* __restrict__ gamma,
               const float* __restrict__ beta, float* __restrict__ Y,
               __half* __restrict__ Yh)
{
    const int row = blockIdx.x;
    const int tid = threadIdx.x;
    const float4 v = ((const float4*)(X + (size_t)row * Esz))[tid];
    float s  = v.x + v.y + v.z + v.w;
    float ss = v.x * v.x + v.y * v.y + v.z * v.z + v.w * v.w;
#pragma unroll
    for (int off = 16; off; off >>= 1) {
        s  += __shfl_xor_sync(0xffffffffu, s,  off);
        ss += __shfl_xor_sync(0xffffffffu, ss, off);
    }
    __shared__ float sh[16];
    const int w = tid >> 5, lane = tid & 31;
    if (lane == 0) { sh[w] = s; sh[w + 8] = ss; }
    __syncthreads();
    if (tid == 0) {
        float S = 0.f, SS = 0.f;
#pragma unroll
        for (int i = 0; i < 8; i++) { S += sh[i]; SS += sh[i + 8]; }
        float mean = S * (1.f / Esz);
        float var  = SS * (1.f / Esz) - mean * mean;
        sh[0] = mean;
        sh[1] = rsqrtf(var + 1e-10f);
    }
    __syncthreads();
    const float mean = sh[0], inv = sh[1];
    const float4 gg = ((const float4*)gamma)[tid];
    const float4 be = ((const float4*)beta)[tid];
    float4 y;
    y.x = gg.x * (v.x - mean) * inv + be.x;
    y.y = gg.y * (v.y - mean) * inv + be.y;
    y.z = gg.z * (v.z - mean) * inv + be.z;
    y.w = gg.w * (v.w - mean) * inv + be.w;
    ((float4*)(Y + (size_t)row * Esz))[tid] = y;
    if (Yh) {
        ((__half2*)(Yh + (size_t)row * Esz))[2 * tid]     = __floats2half2_rn(y.x, y.y);
        ((__half2*)(Yh + (size_t)row * Esz))[2 * tid + 1] = __floats2half2_rn(y.z, y.w);
    }
}

// ================= launch =================
extern "C" void kernel_launch(void* const* d_in, const int* in_sizes, int n_in,
                              void* d_out, int out_size)
{
    const float* x   = (const float*)d_in[0];
    const float* Wq  = (const float*)d_in[1];
    const float* bq  = (const float*)d_in[2];
    const float* Wk  = (const float*)d_in[3];
    const float* bk  = (const float*)d_in[4];
    const float* Wv  = (const float*)d_in[5];
    const float* bv  = (const float*)d_in[6];
    const float* Wo  = (const float*)d_in[7];
    const float* bo  = (const float*)d_in[8];
    const float* W1  = (const float*)d_in[9];
    const float* b1  = (const float*)d_in[10];
    const float* W2  = (const float*)d_in[11];
    const float* b2  = (const float*)d_in[12];
    const float* g1  = (const float*)d_in[13];
    const float* be1 = (const float*)d_in[14];
    const float* g2  = (const float*)d_in[15];
    const float* be2 = (const float*)d_in[16];
    float* out = (float*)d_out;

    float *res1, *ln1, *res2, *bqkv;
    __half *xh, *qkvh, *atth, *ln1h, *hidh, *wqkvT, *woT, *w1T, *w2T;
    cudaGetSymbolAddress((void**)&res1,  g_res1);
    cudaGetSymbolAddress((void**)&ln1,   g_ln1);
    cudaGetSymbolAddress((void**)&res2,  g_res2);
    cudaGetSymbolAddress((void**)&bqkv,  g_bqkv);
    cudaGetSymbolAddress((void**)&xh,    g_xh);
    cudaGetSymbolAddress((void**)&qkvh,  g_qkvh);
    cudaGetSymbolAddress((void**)&atth,  g_atth);
    cudaGetSymbolAddress((void**)&ln1h,  g_ln1h);
    cudaGetSymbolAddress((void**)&hidh,  g_hidh);
    cudaGetSymbolAddress((void**)&wqkvT, g_wqkvT);
    cudaGetSymbolAddress((void**)&woT,   g_woT);
    cudaGetSymbolAddress((void**)&w1T,   g_w1T);
    cudaGetSymbolAddress((void**)&w2T,   g_w2T);

    cudaFuncSetAttribute(gemm_h<0,0,1>, cudaFuncAttributeMaxDynamicSharedMemorySize, GSMEM_BYTES);
    cudaFuncSetAttribute(gemm_h<2,1,0>, cudaFuncAttributeMaxDynamicSharedMemorySize, GSMEM_BYTES);
    cudaFuncSetAttribute(gemm_h<1,0,1>, cudaFuncAttributeMaxDynamicSharedMemorySize, GSMEM_BYTES);
    cudaFuncSetAttribute(attn_mma, cudaFuncAttributeMaxDynamicSharedMemorySize, ATT_SMEM_BYTES);

    // launch 0: x -> half
    prep_x<<<8192, dim3(32, 8)>>>(x, xh);
    // launch 1: weight transposes + bias concat
    prep_w<<<12289, dim3(32, 8)>>>(Wq, Wk, Wv, wqkvT, Wo, woT,
                                   W1, w1T, W2, w2T, bq, bk, bv, bqkv);

    const dim3 blk(128);

    // launch 2: merged QKV (N = 3072)
    gemm_h<0,0,1><<<dim3(3 * Esz / 128, Msz / 128), blk, GSMEM_BYTES>>>(
        xh, wqkvT, bqkv, nullptr, nullptr, qkvh, Msz, 3 * Esz, Esz);

    // launch 3: attention  <-- ncu captures my index 3
    attn_mma<<<dim3(Lsz / 128, Hsz, Bsz), 256, ATT_SMEM_BYTES>>>(
        qkvh, qkvh + Esz, qkvh + 2 * Esz, atth, 3 * Esz);

    // launch 4: O-projection + residual x
    gemm_h<2,1,0><<<dim3(Esz / 128, Msz / 128), blk, GSMEM_BYTES>>>(
        atth, woT, bo, x, res1, nullptr, Msz, Esz, Esz);
    // launch 5: LN1
    ln_kernel<<<Msz, 256>>>(res1, g1, be1, ln1, ln1h);

    // launch 6: FFN1 (relu, half out)
    gemm_h<1,0,1><<<dim3(FFsz / 128, Msz / 128), blk, GSMEM_BYTES>>>(
        ln1h, w1T, b1, nullptr, nullptr, hidh, Msz, FFsz, Esz);
    // launch 7: FFN2 + residual ln1
    gemm_h<2,1,0><<<dim3(Esz / 128, Msz / 128), blk, GSMEM_BYTES>>>(
        hidh, w2T, b2, ln1, res2, nullptr, Msz, Esz, FFsz);
    ln_kernel<<<Msz, 256>>>(res2, g2, be2, out, nullptr);
}

// round 17
// speedup vs baseline: 1.2490x; 1.0244x over previous
#include <cuda_runtime.h>
#include <cuda_fp16.h>
#include <cstdint>
#include <math.h>

#define Bsz 8
#define Lsz 1024
#define Esz 1024
#define Hsz 16
#define DHsz 64
#define FFsz 4096
#define Msz (Bsz*Lsz) /* 8192 */

// ---------------- scratch (device globals; no allocation) ----------------
__device__ __align__(256) float  g_res1[Msz*Esz];
__device__ __align__(256) float  g_ln1[Msz*Esz];
__device__ __align__(256) float  g_res2[Msz*Esz];
__device__ __align__(256) __half g_xh[Msz*Esz];
__device__ __align__(256) __half g_qkvh[(size_t)Msz*3*Esz];
__device__ __align__(256) __half g_atth[Msz*Esz];
__device__ __align__(256) __half g_ln1h[Msz*Esz];
__device__ __align__(256) __half g_hidh[(size_t)Msz*FFsz];
__device__ __align__(256) __half g_wqkvT[(size_t)3*Esz*Esz];
__device__ __align__(256) float  g_bqkv[3*Esz];
__device__ __align__(256) __half g_woT[Esz*Esz];
__device__ __align__(256) __half g_w1T[(size_t)FFsz*Esz];
__device__ __align__(256) __half g_w2T[(size_t)Esz*FFsz];

// ---------------- helpers ----------------
__device__ __forceinline__ uint32_t smem_u32(const void* p) {
    uint32_t a;
    asm("{ .reg .u64 t; cvta.to.shared.u64 t, %1; cvt.u32.u64 %0, t; }" : "=r"(a) : "l"(p));
    return a;
}
#define CP16(dst, src) \
    asm volatile("cp.async.cg.shared.global [%0], [%1], 16;" :: "r"(dst), "l"(src))
#define CP_COMMIT() asm volatile("cp.async.commit_group;" ::: "memory")
#define CP_WAIT1()  asm volatile("cp.async.wait_group 1;"  ::: "memory")
#define CP_WAIT0()  asm volatile("cp.async.wait_group 0;"  ::: "memory")

__device__ __forceinline__ void ldsm4(uint32_t* r, uint32_t addr) {
    asm volatile("ldmatrix.sync.aligned.m8n8.x4.shared.b16 {%0,%1,%2,%3}, [%4];"
        : "=r"(r[0]), "=r"(r[1]), "=r"(r[2]), "=r"(r[3]) : "r"(addr));
}
__device__ __forceinline__ void ldsm4t(uint32_t* r, uint32_t addr) {
    asm volatile("ldmatrix.sync.aligned.m8n8.x4.trans.shared.b16 {%0,%1,%2,%3}, [%4];"
        : "=r"(r[0]), "=r"(r[1]), "=r"(r[2]), "=r"(r[3]) : "r"(addr));
}
__device__ __forceinline__ void mma16(float* c, const uint32_t* a, const uint32_t* b) {
    asm volatile(
        "mma.sync.aligned.m16n8k16.row.col.f32.f16.f16.f32 "
        "{%0,%1,%2,%3}, {%4,%5,%6,%7}, {%8,%9}, {%0,%1,%2,%3};"
        : "+f"(c[0]), "+f"(c[1]), "+f"(c[2]), "+f"(c[3])
        : "r"(a[0]), "r"(a[1]), "r"(a[2]), "r"(a[3]), "r"(b[0]), "r"(b[1]));
}
__device__ __forceinline__ uint32_t packh2(float a, float b) {
    __half2 h = __floats2half2_rn(a, b);
    return *(uint32_t*)&h;
}
__device__ __forceinline__ float ex2f(float x) {
    float r; asm("ex2.approx.f32 %0, %1;" : "=f"(r) : "f"(x)); return r;
}

// ================= fp16 GEMM: CTA 128x128, 4 warps of 64x64, 3 stages ====
#define GROW_B 144
#define GTILE_B (128 * GROW_B)        /* 18432 */
#define GSTAGE_B (2 * GTILE_B)        /* 36864 */
#define GSMEM_BYTES (3 * GSTAGE_B)    /* 110592 */

template<int EPI, int WF32, int WH>
__global__ __launch_bounds__(128, 2)
void gemm_h(const __half* __restrict__ A, const __half* __restrict__ Bt,
            const float* __restrict__ bias, const float* __restrict__ R,
            float* __restrict__ C, __half* __restrict__ Ch, int M, int N, int K)
{
    extern __shared__ __align__(16) char hs[];
    const uint32_t sbase = smem_u32(hs);

    const int tid  = threadIdx.x;
    const int lane = tid & 31;
    const int wid  = tid >> 5;          // 0..3
    const int g    = lane >> 2;
    const int tig  = lane & 3;
    const int wm   = (wid & 1) * 64;
    const int wn   = (wid >> 1) * 64;
    const int m0   = blockIdx.y * 128;
    const int n0   = blockIdx.x * 128;

    const __half* Ab = A  + (size_t)m0 * K;
    const __half* Bb = Bt + (size_t)n0 * K;

    auto load_piece = [&](int s, int k0, int piece) {
        const uint32_t sa = sbase + (uint32_t)s * GSTAGE_B;
        const uint32_t sb = sa + GTILE_B;
#pragma unroll
        for (int i = piece * 2; i < piece * 2 + 2; i++) {
            const int id = i * 128 + tid;          // 0..1023
            const int row = id >> 3, c = id & 7;
            const uint32_t off = (uint32_t)row * GROW_B + (uint32_t)c * 16;
            CP16(sa + off, Ab + (size_t)row * K + k0 + c * 8);
            CP16(sb + off, Bb + (size_t)row * K + k0 + c * 8);
        }
    };

    const int a_r  = wm + (lane & 15);
    const int a_c  = 8 * (lane >> 4);
    const int b_r  = wn + (lane & 7) + ((lane >> 4) & 1) * 8;   // + p*16
    const int b_c  = 8 * ((lane >> 3) & 1);

    float acc[4][8][4];
#pragma unroll
    for (int i = 0; i < 4; i++)
#pragma unroll
        for (int j = 0; j < 8; j++)
#pragma unroll
            for (int l = 0; l < 4; l++) acc[i][j][l] = 0.f;

    const int nch = K >> 6;   // 64-half chunks
#pragma unroll
    for (int p = 0; p < 4; p++) load_piece(0, 0, p);
    CP_COMMIT();
#pragma unroll
    for (int p = 0; p < 4; p++) load_piece(1, 64, p);
    CP_COMMIT();

    for (int i = 0; i < nch; i++) {
        if (i + 1 < nch) { CP_WAIT1(); } else { CP_WAIT0(); }
        __syncthreads();   // single barrier per chunk

        const bool pf = (i + 2 < nch);
        const int  ps = (i + 2) % 3;
        const int  pk = (i + 2) * 64;

        const uint32_t sa = sbase + (uint32_t)(i % 3) * GSTAGE_B;
        const uint32_t sb = sa + GTILE_B;
#pragma unroll
        for (int kk = 0; kk < 4; kk++) {
            if (pf) load_piece(ps, pk, kk);   // spread cp.async across kk groups
            const int kh = kk * 16;
            uint32_t a[4][4];
#pragma unroll
            for (int mt = 0; mt < 4; mt++)
                ldsm4(a[mt], sa + (uint32_t)(a_r + mt * 16) * GROW_B + (uint32_t)(kh + a_c) * 2);
            uint32_t bf[4][4];
#pragma unroll
            for (int p = 0; p < 4; p++)
                ldsm4(bf[p], sb + (uint32_t)(b_r + p * 16) * GROW_B + (uint32_t)(kh + b_c) * 2);
#pragma unroll
            for (int mt = 0; mt < 4; mt++)
#pragma unroll
                for (int p = 0; p < 4; p++) {
                    mma16(acc[mt][2 * p],     a[mt], &bf[p][0]);
                    mma16(acc[mt][2 * p + 1], a[mt], &bf[p][2]);
                }
        }
        CP_COMMIT();   // one group per iteration (empty near tail is fine)
    }

#pragma unroll
    for (int mt = 0; mt < 4; mt++) {
        const int r0 = m0 + wm + mt * 16 + g;
        const int r1 = r0 + 8;
#pragma unroll
        for (int nt = 0; nt < 8; nt++) {
            const int c0 = n0 + wn + nt * 8 + 2 * tig;
            const float2 bb = *(const float2*)(bias + c0);
            float v00 = acc[mt][nt][0] + bb.x;
            float v01 = acc[mt][nt][1] + bb.y;
            float v10 = acc[mt][nt][2] + bb.x;
            float v11 = acc[mt][nt][3] + bb.y;
            if (EPI == 1) {
                v00 = fmaxf(v00, 0.f); v01 = fmaxf(v01, 0.f);
                v10 = fmaxf(v10, 0.f); v11 = fmaxf(v11, 0.f);
            }
            if (EPI == 2) {
                const float2 q0 = *(const float2*)(R + (size_t)r0 * N + c0);
                const float2 q1 = *(const float2*)(R + (size_t)r1 * N + c0);
                v00 += q0.x; v01 += q0.y; v10 += q1.x; v11 += q1.y;
            }
            if (WF32) {
                *(float2*)(C + (size_t)r0 * N + c0) = make_float2(v00, v01);
                *(float2*)(C + (size_t)r1 * N + c0) = make_float2(v10, v11);
            }
            if (WH) {
                *(__half2*)(Ch + (size_t)r0 * N + c0) = __floats2half2_rn(v00, v01);
                *(__half2*)(Ch + (size_t)r1 * N + c0) = __floats2half2_rn(v10, v11);
            }
        }
    }
}

// ================= tensor-core flash attention (exp2-folded softmax, l via ones-MMA)
#define AQ_H   (128 * 72)
#define AKV_H  (64 * 72)
#define ATT_SMEM_BYTES ((AQ_H + 4 * AKV_H) * 2)   /* 55296 */

__global__ __launch_bounds__(256)
void attn_mma(const __half* __restrict__ Qh, const __half* __restrict__ Kh,
              const __half* __restrict__ Vh, __half* __restrict__ O, int ldq)
{
    extern __shared__ __align__(16) __half ash[];
    const uint32_t sb = smem_u32(ash);
    const uint32_t sQ = sb;

    const int qt = blockIdx.x, h = blockIdx.y, b = blockIdx.z;
    const int tid  = threadIdx.x;
    const int lane = tid & 31;
    const int wid  = tid >> 5;
    const int g    = lane >> 2;
    const int tig  = lane & 3;
    const int wq   = wid * 16;

    const size_t qgbase = ((size_t)(b * Lsz + qt * 128)) * ldq + h * 64;

    auto sKs = [&](int s) { return sb + (uint32_t)(AQ_H + s * AKV_H) * 2; };
    auto sVs = [&](int s) { return sb + (uint32_t)(AQ_H + 2 * AKV_H + s * AKV_H) * 2; };

    auto loadQ = [&]() {
#pragma unroll
        for (int i = 0; i < 4; i++) {
            const int id = i * 256 + tid;
            const int row = id >> 3, cc = id & 7;
            CP16(sQ + (uint32_t)row * 144 + (uint32_t)cc * 16,
                 Qh + qgbase + (size_t)row * ldq + cc * 8);
        }
    };
    auto loadKV = [&](int s, int t) {
        const size_t kb = ((size_t)(b * Lsz + t * 64)) * ldq + h * 64;
#pragma unroll
        for (int i = 0; i < 2; i++) {
            const int id = i * 256 + tid;
            const int row = id >> 3, cc = id & 7;
            const uint32_t off = (uint32_t)row * 144 + (uint32_t)cc * 16;
            CP16(sKs(s) + off, Kh + kb + (size_t)row * ldq + cc * 8);
            CP16(sVs(s) + off, Vh + kb + (size_t)row * ldq + cc * 8);
        }
    };

    const uint32_t qa_row = (uint32_t)(wq + (lane & 15));
    const uint32_t qa_col = (uint32_t)(8 * (lane >> 4));
    const uint32_t kb_row = (uint32_t)((lane & 7) + ((lane >> 4) & 1) * 8);
    const uint32_t kb_col = (uint32_t)(8 * ((lane >> 3) & 1));
    const uint32_t vt_row = (uint32_t)((lane & 7) + ((lane >> 3) & 1) * 8);
    const uint32_t vt_col = (uint32_t)((lane >> 4) * 8);

    uint32_t qf[4][4];
    float oacc[8][4];
#pragma unroll
    for (int t = 0; t < 8; t++)
#pragma unroll
        for (int i = 0; i < 4; i++) oacc[t][i] = 0.f;
    float lacc[4] = {0.f, 0.f, 0.f, 0.f};          // row-sum accumulators via ones-MMA
    float m0 = -1e30f, m1 = -1e30f;
    const float cls = 0.125f * 1.4426950408889634f; // scale * log2(e)
    const uint32_t onesf[2] = {0x3C003C00u, 0x3C003C00u};  // fp16 ones B fragment

    loadQ(); loadKV(0, 0); CP_COMMIT();
    loadKV(1, 1); CP_COMMIT();

    for (int t = 0; t < Lsz / 64; t++) {
        const int s = t & 1;
        if (t + 1 < Lsz / 64) { CP_WAIT1(); } else { CP_WAIT0(); }
        __syncthreads();

        if (t == 0) {
#pragma unroll
            for (int ks = 0; ks < 4; ks++)
                ldsm4(qf[ks], sQ + qa_row * 144 + (qa_col + 16 * ks) * 2);
        }

        float sacc[8][4];
#pragma unroll
        for (int n = 0; n < 8; n++)
#pragma unroll
            for (int i = 0; i < 4; i++) sacc[n][i] = 0.f;
#pragma unroll
        for (int ks = 0; ks < 4; ks++) {
#pragma unroll
            for (int g16 = 0; g16 < 4; g16++) {
                uint32_t kf[4];
                ldsm4(kf, sKs(s) + (kb_row + g16 * 16) * 144 + (kb_col + 16 * ks) * 2);
                mma16(sacc[2 * g16],     qf[ks], &kf[0]);
                mma16(sacc[2 * g16 + 1], qf[ks], &kf[2]);
            }
        }

        // max in RAW score domain (no per-element scaling)
        float mx0 = -1e30f, mx1 = -1e30f;
#pragma unroll
        for (int n = 0; n < 8; n++) {
            mx0 = fmaxf(mx0, fmaxf(sacc[n][0], sacc[n][1]));
            mx1 = fmaxf(mx1, fmaxf(sacc[n][2], sacc[n][3]));
        }
        mx0 = fmaxf(mx0, __shfl_xor_sync(0xffffffffu, mx0, 1));
        mx0 = fmaxf(mx0, __shfl_xor_sync(0xffffffffu, mx0, 2));
        mx1 = fmaxf(mx1, __shfl_xor_sync(0xffffffffu, mx1, 1));
        mx1 = fmaxf(mx1, __shfl_xor_sync(0xffffffffu, mx1, 2));

        const float mn0 = fmaxf(m0, mx0), mn1 = fmaxf(m1, mx1);
        const float c0 = ex2f((m0 - mn0) * cls);
        const float c1 = ex2f((m1 - mn1) * cls);
        m0 = mn0; m1 = mn1;
        const float b0 = -mn0 * cls, b1 = -mn1 * cls;

        // p = exp2(s*cls - m*cls) : one FMA + one EX2 per element
        uint32_t ph[8][2];
#pragma unroll
        for (int n = 0; n < 8; n++) {
            const float p00 = ex2f(fmaf(sacc[n][0], cls, b0));
            const float p01 = ex2f(fmaf(sacc[n][1], cls, b0));
            const float p10 = ex2f(fmaf(sacc[n][2], cls, b1));
            const float p11 = ex2f(fmaf(sacc[n][3], cls, b1));
            ph[n][0] = packh2(p00, p01);
            ph[n][1] = packh2(p10, p11);
        }

        // rescale running O and l by correction factors
        lacc[0] *= c0; lacc[1] *= c0; lacc[2] *= c1; lacc[3] *= c1;
#pragma unroll
        for (int n = 0; n < 8; n++) {
            oacc[n][0] *= c0; oacc[n][1] *= c0;
            oacc[n][2] *= c1; oacc[n][3] *= c1;
        }

        // O += P V ; l += P * ones (MMA does the cross-lane row reduction)
#pragma unroll
        for (int j = 0; j < 4; j++) {
            const uint32_t pa[4] = { ph[2 * j][0], ph[2 * j][1],
                                     ph[2 * j + 1][0], ph[2 * j + 1][1] };
#pragma unroll
            for (int g16 = 0; g16 < 4; g16++) {
                uint32_t vf[4];
                ldsm4t(vf, sVs(s) + (vt_row + j * 16) * 144 + (vt_col + g16 * 16) * 2);
                mma16(oacc[2 * g16],     pa, &vf[0]);
                mma16(oacc[2 * g16 + 1], pa, &vf[2]);
            }
            mma16(lacc, pa, onesf);
        }

        __syncthreads();
        if (t + 2 < Lsz / 64) { loadKV(s, t + 2); CP_COMMIT(); }
    }

    const float i0 = 1.f / lacc[0], i1 = 1.f / lacc[2];
    const size_t r0 = (size_t)(b * Lsz + qt * 128 + wq + g) * Esz + h * 64;
    const size_t r1 = r0 + (size_t)8 * Esz;
#pragma unroll
    for (int n = 0; n < 8; n++) {
        const int col = 8 * n + 2 * tig;
        *(__half2*)(O + r0 + col) = __floats2half2_rn(oacc[n][0] * i0, oacc[n][1] * i0);
        *(__half2*)(O + r1 + col) = __floats2half2_rn(oacc[n][2] * i1, oacc[n][3] * i1);
    }
}

// ================= prep, split in two =================
__global__ void prep_x(const float* __restrict__ x, __half* __restrict__ xh)
{
    const int i = blockIdx.x * 256 + threadIdx.y * 32 + threadIdx.x;
    const float4 v = ((const float4*)x)[i];
    ((__half2*)xh)[2 * i]     = __floats2half2_rn(v.x, v.y);
    ((__half2*)xh)[2 * i + 1] = __floats2half2_rn(v.z, v.w);
}

__device__ __forceinline__ void tr_body(const float* in, __half* out, int K, int N,
                                        int k0, int n0, int tx, int ty)
{
    __shared__ float t[32][33];
#pragma unroll
    for (int i = 0; i < 4; i++)
        t[ty + 8 * i][tx] = in[(size_t)(k0 + ty + 8 * i) * N + n0 + tx];
    __syncthreads();
#pragma unroll
    for (int i = 0; i < 4; i++)
        out[(size_t)(n0 + ty + 8 * i) * K + k0 + tx] = __float2half_rn(t[tx][ty + 8 * i]);
}

__global__ void prep_w(const float* __restrict__ Wq,  const float* __restrict__ Wk,
                       const float* __restrict__ Wv,  __half* __restrict__ wqkvT,
                       const float* __restrict__ Wo,  __half* __restrict__ woT,
                       const float* __restrict__ W1,  __half* __restrict__ w1T,
                       const float* __restrict__ W2,  __half* __restrict__ w2T,
                       const float* __restrict__ bq,  const float* __restrict__ bk,
                       const float* __restrict__ bv,  float* __restrict__ bqkv)
{
    const int tx = threadIdx.x, ty = threadIdx.y;
    int bx = blockIdx.x;
    if (bx < 3072) {   // headed QKV transposes -> combined [3072][1024]
        const int which = bx >> 10;
        const int r = bx & 1023;
        const int e0 = (r & 31) * 32, d0 = ((r >> 5) & 1) * 32, h = r >> 6;
        const float* W = (which == 0) ? Wq : (which == 1) ? Wk : Wv;
        __shared__ float t[32][33];
        const float* ih = W + (size_t)h * Esz * 64;
#pragma unroll
        for (int i = 0; i < 4; i++)
            t[ty + 8 * i][tx] = ih[(size_t)(e0 + ty + 8 * i) * 64 + d0 + tx];
        __syncthreads();
#pragma unroll
        for (int i = 0; i < 4; i++)
            wqkvT[(size_t)(which * Esz + h * 64 + d0 + ty + 8 * i) * Esz + e0 + tx] =
                __float2half_rn(t[tx][ty + 8 * i]);
        return;
    }
    bx -= 3072;
    if (bx < 1024) { tr_body(Wo, woT, Esz, Esz, (bx & 31) * 32, (bx >> 5) * 32, tx, ty); return; }
    bx -= 1024;
    if (bx < 4096) { tr_body(W1, w1T, Esz, FFsz, (bx & 31) * 32, (bx >> 5) * 32, tx, ty); return; }
    bx -= 4096;
    if (bx < 4096) { tr_body(W2, w2T, FFsz, Esz, (bx & 127) * 32, (bx >> 7) * 32, tx, ty); return; }
    const int id = ty * 32 + tx;
#pragma unroll
    for (int j = 0; j < 12; j++) {
        const int idx = j * 256 + id;
        bqkv[idx] = (idx < 1024) ? bq[idx] : (idx < 2048) ? bk[idx - 1024] : bv[idx - 2048];
    }
}

// ================= layer norm =================
__global__ __launch_bounds__(256)
void ln_kernel(const float* __restrict__ X, const float* __restrict__ gamma,
               const float* __restrict__ beta, float* __restrict__ Y,
               __half* __restrict__ Yh)
{
    const int row = blockIdx.x;
    const int tid = threadIdx.x;
    const float4 v = ((const float4*)(X + (size_t)row * Esz))[tid];
    float s  = v.x + v.y + v.z + v.w;
    float ss = v.x * v.x + v.y * v.y + v.z * v.z + v.w * v.w;
#pragma unroll
    for (int off = 16; off; off >>= 1) {
        s  += __shfl_xor_sync(0xffffffffu, s,  off);
        ss += __shfl_xor_sync(0xffffffffu, ss, off);
    }
    __shared__ float sh[16];
    const int w = tid >> 5, lane = tid & 31;
    if (lane == 0) { sh[w] = s; sh[w + 8] = ss; }
    __syncthreads();
    if (tid == 0) {
        float S = 0.f, SS = 0.f;
#pragma unroll
        for (int i = 0; i < 8; i++) { S += sh[i]; SS += sh[i + 8]; }
        float mean = S * (1.f / Esz);
        float var  = SS * (1.f / Esz) - mean * mean;
        sh[0] = mean;
        sh[1] = rsqrtf(var + 1e-10f);
    }
    __syncthreads();
    const float mean = sh[0], inv = sh[1];
    const float4 gg = ((const float4*)gamma)[tid];
    const float4 be = ((const float4*)beta)[tid];
    float4 y;
    y.x = gg.x * (v.x - mean) * inv + be.x;
    y.y = gg.y * (v.y - mean) * inv + be.y;
    y.z = gg.z * (v.z - mean) * inv + be.z;
    y.w = gg.w * (v.w - mean) * inv + be.w;
    ((float4*)(Y + (size_t)row * Esz))[tid] = y;
    if (Yh) {
        ((__half2*)(Yh + (size_t)row * Esz))[2 * tid]     = __floats2half2_rn(y.x, y.y);
        ((__half2*)(Yh + (size_t)row * Esz))[2 * tid + 1] = __floats2half2_rn(y.z, y.w);
    }
}

// ================= launch =================
extern "C" void kernel_launch(void* const* d_in, const int* in_sizes, int n_in,
                              void* d_out, int out_size)
{
    const float* x   = (const float*)d_in[0];
    const float* Wq  = (const float*)d_in[1];
    const float* bq  = (const float*)d_in[2];
    const float* Wk  = (const float*)d_in[3];
    const float* bk  = (const float*)d_in[4];
    const float* Wv  = (const float*)d_in[5];
    const float* bv  = (const float*)d_in[6];
    const float* Wo  = (const float*)d_in[7];
    const float* bo  = (const float*)d_in[8];
    const float* W1  = (const float*)d_in[9];
    const float* b1  = (const float*)d_in[10];
    const float* W2  = (const float*)d_in[11];
    const float* b2  = (const float*)d_in[12];
    const float* g1  = (const float*)d_in[13];
    const float* be1 = (const float*)d_in[14];
    const float* g2  = (const float*)d_in[15];
    const float* be2 = (const float*)d_in[16];
    float* out = (float*)d_out;

    float *res1, *ln1, *res2, *bqkv;
    __half *xh, *qkvh, *atth, *ln1h, *hidh, *wqkvT, *woT, *w1T, *w2T;
    cudaGetSymbolAddress((void**)&res1,  g_res1);
    cudaGetSymbolAddress((void**)&ln1,   g_ln1);
    cudaGetSymbolAddress((void**)&res2,  g_res2);
    cudaGetSymbolAddress((void**)&bqkv,  g_bqkv);
    cudaGetSymbolAddress((void**)&xh,    g_xh);
    cudaGetSymbolAddress((void**)&qkvh,  g_qkvh);
    cudaGetSymbolAddress((void**)&atth,  g_atth);
    cudaGetSymbolAddress((void**)&ln1h,  g_ln1h);
    cudaGetSymbolAddress((void**)&hidh,  g_hidh);
    cudaGetSymbolAddress((void**)&wqkvT, g_wqkvT);
    cudaGetSymbolAddress((void**)&woT,   g_woT);
    cudaGetSymbolAddress((void**)&w1T,   g_w1T);
    cudaGetSymbolAddress((void**)&w2T,   g_w2T);

    cudaFuncSetAttribute(gemm_h<0,0,1>, cudaFuncAttributeMaxDynamicSharedMemorySize, GSMEM_BYTES);
    cudaFuncSetAttribute(gemm_h<2,1,0>, cudaFuncAttributeMaxDynamicSharedMemorySize, GSMEM_BYTES);
    cudaFuncSetAttribute(gemm_h<1,0,1>, cudaFuncAttributeMaxDynamicSharedMemorySize, GSMEM_BYTES);
    cudaFuncSetAttribute(attn_mma, cudaFuncAttributeMaxDynamicSharedMemorySize, ATT_SMEM_BYTES);

    // launch 0: x -> half
    prep_x<<<8192, dim3(32, 8)>>>(x, xh);
    // launch 1: weight transposes + bias concat
    prep_w<<<12289, dim3(32, 8)>>>(Wq, Wk, Wv, wqkvT, Wo, woT,
                                   W1, w1T, W2, w2T, bq, bk, bv, bqkv);

    const dim3 blk(128);

    // launch 2: merged QKV (N = 3072)
    gemm_h<0,0,1><<<dim3(3 * Esz / 128, Msz / 128), blk, GSMEM_BYTES>>>(
        xh, wqkvT, bqkv, nullptr, nullptr, qkvh, Msz, 3 * Esz, Esz);

    // launch 3: attention  <-- profiled slot
    attn_mma<<<dim3(Lsz / 128, Hsz, Bsz), 256, ATT_SMEM_BYTES>>>(
        qkvh, qkvh + Esz, qkvh + 2 * Esz, atth, 3 * Esz);

    // launch 4: O-projection + residual x
    gemm_h<2,1,0><<<dim3(Esz / 128, Msz / 128), blk, GSMEM_BYTES>>>(
        atth, woT, bo, x, res1, nullptr, Msz, Esz, Esz);
    // launch 5: LN1
    ln_kernel<<<Msz, 256>>>(res1, g1, be1, ln1, ln1h);

    // launch 6: FFN1 (relu, half out)
    gemm_h<1,0,1><<<dim3(FFsz / 128, Msz / 128), blk, GSMEM_BYTES>>>(
        ln1h, w1T, b1, nullptr, nullptr, hidh, Msz, FFsz, Esz);
    // launch 7: FFN2 + residual ln1
    gemm_h<2,1,0><<<dim3(Esz / 128, Msz / 128), blk, GSMEM_BYTES>>>(
        hidh, w2T, b2, ln1, res2, nullptr, Msz, Esz, FFsz);
    ln_kernel<<<Msz, 256>>>(res2, g2, be2, out, nullptr);
}